// round 2
// baseline (speedup 1.0000x reference)
#include <cuda_runtime.h>
#include <math.h>

// Problem constants
#define Bt   32
#define Ct   684
#define Ht   16
#define Wt   64
#define HWt  1024
#define HIDt 256
#define At   512
#define Kt   11
#define NPATCH 121          // 11*11
#define KCOMB 805           // 684 + 121
#define KPAD  808           // padded to multiple of 8

// Output layout in d_out (tuple order, flattened):
//  [0, 21888)            context_vector [32,684]
//  [21888, 54656)        alpha          [32,16,64]
//  [54656, 87424)        alpha_sum_new  [32,1,16,64]
#define CTX_N   (Bt*Ct)
#define ALPHA_OFF CTX_N
#define ASUM_OFF  (CTX_N + Bt*HWt)

// ---------- scratch (device globals; no allocation allowed) ----------
__device__ float g_query[Bt * At];              // 64 KB
__device__ float g_Wcomb[KPAD * At];            // 1.65 MB, layout [k][a]
__device__ float g_P[Bt * NPATCH * HWt];        // 15.9 MB, im2col patches [b][j][pos]
__device__ float g_Epart[4 * Bt * HWt];         // 512 KB, partial energies per a-tile
__device__ float g_E[Bt * HWt];                 // 128 KB
__device__ float g_bmax[Bt];
__device__ float g_gmax;

// ---------- prep: query = hidden @ Wh^T + bh ----------
__global__ void k_query(const float* __restrict__ hidden,
                        const float* __restrict__ Wh,
                        const float* __restrict__ bh) {
    int b = blockIdx.x, tid = threadIdx.x;
    __shared__ float h[HIDt];
    if (tid < HIDt) h[tid] = hidden[b * HIDt + tid];
    __syncthreads();
    for (int a = tid; a < At; a += 256) {
        const float* wr = Wh + a * HIDt;
        float s = 0.f;
        #pragma unroll 8
        for (int k = 0; k < HIDt; ++k) s = fmaf(wr[k], h[k], s);
        g_query[b * At + a] = s + bh[a];
    }
}

// ---------- prep: Wcomb rows [0,684) = Wec^T ; zero pad rows [805,808) ----------
__global__ void k_tw(const float* __restrict__ Wec) {
    int idx = blockIdx.x * 256 + threadIdx.x;
    const int n1 = Ct * At;
    if (idx < n1) {
        int k = idx / At, a = idx - k * At;
        g_Wcomb[idx] = Wec[a * Ct + k];
    } else if (idx < n1 + 3 * At) {
        g_Wcomb[KCOMB * At + (idx - n1)] = 0.f;
    }
}

// ---------- prep: Wcomb rows [684,805) = Weff^T,  Weff[a,j] = sum_k Waw[a,k]*Wac[k,j] ----------
__global__ void k_weff(const float* __restrict__ Waw,
                       const float* __restrict__ Wac) {
    int a = blockIdx.x, j = threadIdx.x;
    if (j >= NPATCH) return;
    float s = 0.f;
    for (int k = 0; k < At; ++k)
        s = fmaf(Waw[a * At + k], Wac[k * NPATCH + j], s);
    g_Wcomb[(Ct + j) * At + a] = s;
}

// ---------- prep: im2col of alpha_sum (11x11 patches, pad 5) ----------
__global__ void k_patches(const float* __restrict__ asum) {
    int idx = blockIdx.x * 256 + threadIdx.x;
    if (idx >= Bt * NPATCH * HWt) return;
    int pos = idx & (HWt - 1);
    int t = idx >> 10;
    int j = t % NPATCH;
    int b = t / NPATCH;
    int h = pos >> 6, w = pos & 63;
    int hh = h + (j / Kt) - 5;
    int ww = w + (j % Kt) - 5;
    float v = 0.f;
    if (hh >= 0 && hh < Ht && ww >= 0 && ww < Wt)
        v = asum[b * HWt + hh * Wt + ww];
    g_P[idx] = v;
}

// ---------- main fused GEMM + tanh + Wv reduction ----------
// C[pos,a] = sum_k X[k,pos] * Wcomb[k,a]   (both operands K-major: TN layout)
// X rows: k<684 -> cnn[b,k,:,:] (already [k][pos]!), k>=684 -> g_P[b][k-684][:]
// Epilogue: e[pos] += sum over this block's 128 a of Wv[a]*tanh(acc + query[b,a] + bec[a])
__global__ __launch_bounds__(256, 2)
void k_gemm(const float* __restrict__ cnn,
            const float* __restrict__ bec,
            const float* __restrict__ Wv) {
    const int b    = blockIdx.z;
    const int pos0 = blockIdx.x << 7;   // 8 tiles of 128 positions
    const int a0   = blockIdx.y << 7;   // 4 tiles of 128 outputs

    __shared__ float sh[2048];          // Xs[8][128] | Ws[8][128]; reused for reduction
    float* Xs = sh;
    float* Ws = sh + 1024;

    float acc[8][8];
    #pragma unroll
    for (int i = 0; i < 8; ++i)
        #pragma unroll
        for (int j = 0; j < 8; ++j) acc[i][j] = 0.f;

    const int tid   = threadIdx.x;
    const int ldRow = tid >> 5;            // 0..7
    const int ldCol = (tid & 31) << 2;     // 0..124 step 4
    const int tx    = tid & 15;
    const int ty    = tid >> 4;

    const float* Cb = cnn + b * (Ct * HWt);
    const float* Pb = g_P + b * (NPATCH * HWt);

    for (int it = 0; it < 101; ++it) {     // 101*8 = 808 = KPAD
        int kg = (it << 3) + ldRow;
        int kc = kg > (KCOMB - 1) ? (KCOMB - 1) : kg;  // clamp; padded W rows are zero
        const float* xsrc = (kc < Ct) ? (Cb + (kc << 10)) : (Pb + ((kc - Ct) << 10));
        float4 xv = *(const float4*)(xsrc + pos0 + ldCol);
        float4 wv = *(const float4*)(g_Wcomb + (kg << 9) + a0 + ldCol);
        __syncthreads();
        *(float4*)(Xs + (ldRow << 7) + ldCol) = xv;
        *(float4*)(Ws + (ldRow << 7) + ldCol) = wv;
        __syncthreads();
        #pragma unroll
        for (int kk = 0; kk < 8; ++kk) {
            float4 x0 = *(const float4*)(Xs + (kk << 7) + (ty << 2));
            float4 x1 = *(const float4*)(Xs + (kk << 7) + 64 + (ty << 2));
            float4 w0 = *(const float4*)(Ws + (kk << 7) + (tx << 2));
            float4 w1 = *(const float4*)(Ws + (kk << 7) + 64 + (tx << 2));
            float xr[8] = {x0.x, x0.y, x0.z, x0.w, x1.x, x1.y, x1.z, x1.w};
            float wr[8] = {w0.x, w0.y, w0.z, w0.w, w1.x, w1.y, w1.z, w1.w};
            #pragma unroll
            for (int i = 0; i < 8; ++i)
                #pragma unroll
                for (int j = 0; j < 8; ++j)
                    acc[i][j] = fmaf(xr[i], wr[j], acc[i][j]);
        }
    }

    // epilogue: tanh + dot with Wv over this block's 128 a-values
    float e[8];
    #pragma unroll
    for (int i = 0; i < 8; ++i) e[i] = 0.f;
    #pragma unroll
    for (int j = 0; j < 8; ++j) {
        int aj = a0 + ((j < 4) ? ((tx << 2) + j) : (64 + (tx << 2) + j - 4));
        float qb  = g_query[(b << 9) + aj] + bec[aj];
        float wvv = Wv[aj];
        #pragma unroll
        for (int i = 0; i < 8; ++i)
            e[i] = fmaf(wvv, tanhf(acc[i][j] + qb), e[i]);
    }

    __syncthreads();
    #pragma unroll
    for (int i = 0; i < 8; ++i) {
        int pl = (i < 4) ? ((ty << 2) + i) : (64 + (ty << 2) + i - 4);
        sh[(pl << 4) + tx] = e[i];        // red[128][16]
    }
    __syncthreads();
    if (tid < 128) {
        float s = 0.f;
        #pragma unroll
        for (int t = 0; t < 16; ++t) s += sh[(tid << 4) + t];
        g_Epart[blockIdx.y * (Bt * HWt) + (b << 10) + pos0 + tid] = s;
    }
}

// ---------- reduce 4 a-tile partials, add bv, per-b max ----------
__global__ void k_reduceE(const float* __restrict__ bv) {
    int b = blockIdx.x, tid = threadIdx.x;
    float bvv = bv[0];
    float m = -1e30f;
    for (int p = tid; p < HWt; p += 256) {
        float s = bvv;
        #pragma unroll
        for (int t = 0; t < 4; ++t) s += g_Epart[t * (Bt * HWt) + b * HWt + p];
        g_E[b * HWt + p] = s;
        m = fmaxf(m, s);
    }
    __shared__ float sm[256];
    sm[tid] = m;
    __syncthreads();
    for (int s2 = 128; s2 > 0; s2 >>= 1) {
        if (tid < s2) sm[tid] = fmaxf(sm[tid], sm[tid + s2]);
        __syncthreads();
    }
    if (tid == 0) g_bmax[b] = sm[0];
}

// ---------- global max over 32 per-b maxes ----------
__global__ void k_gmax() {
    float v = g_bmax[threadIdx.x];
    #pragma unroll
    for (int o = 16; o > 0; o >>= 1) v = fmaxf(v, __shfl_xor_sync(0xffffffffu, v, o));
    if (threadIdx.x == 0) g_gmax = v;
}

// ---------- per-b softmax; write alpha and alpha_sum_new ----------
__global__ void k_softmax(const float* __restrict__ mask,
                          const float* __restrict__ asum,
                          float* __restrict__ out) {
    int b = blockIdx.x, tid = threadIdx.x;
    __shared__ float ex[HWt];
    __shared__ float sm[256];
    float gm = g_gmax;
    float ls = 0.f;
    for (int p = tid; p < HWt; p += 256) {
        float v = expf(g_E[b * HWt + p] - gm) * mask[b * HWt + p];
        ex[p] = v;
        ls += v;
    }
    sm[tid] = ls;
    __syncthreads();
    for (int s2 = 128; s2 > 0; s2 >>= 1) {
        if (tid < s2) sm[tid] += sm[tid + s2];
        __syncthreads();
    }
    float inv = 1.f / (sm[0] + 1e-10f);
    for (int p = tid; p < HWt; p += 256) {
        float al = ex[p] * inv;
        out[ALPHA_OFF + b * HWt + p] = al;
        out[ASUM_OFF  + b * HWt + p] = al + asum[b * HWt + p];
    }
}

// ---------- context[b,c] = sum_pos alpha[b,pos] * cnn[b,c,pos] ----------
__global__ void k_context(const float* __restrict__ cnn,
                          float* __restrict__ out) {
    int c = blockIdx.x, b = blockIdx.y, tid = threadIdx.x;
    const float* f  = cnn + (b * Ct + c) * HWt;
    const float* al = out + ALPHA_OFF + b * HWt;
    float s = 0.f;
    for (int p = tid; p < HWt; p += 128) s = fmaf(al[p], f[p], s);
    #pragma unroll
    for (int o = 16; o > 0; o >>= 1) s += __shfl_xor_sync(0xffffffffu, s, o);
    __shared__ float sm[4];
    if ((tid & 31) == 0) sm[tid >> 5] = s;
    __syncthreads();
    if (tid == 0) out[b * Ct + c] = sm[0] + sm[1] + sm[2] + sm[3];
}

// ---------- launch ----------
extern "C" void kernel_launch(void* const* d_in, const int* in_sizes, int n_in,
                              void* d_out, int out_size) {
    const float* cnn    = (const float*)d_in[0];
    const float* hidden = (const float*)d_in[1];
    const float* asum   = (const float*)d_in[2];
    const float* mask   = (const float*)d_in[3];
    const float* Wh     = (const float*)d_in[4];
    const float* bh     = (const float*)d_in[5];
    const float* Wec    = (const float*)d_in[6];
    const float* bec    = (const float*)d_in[7];
    const float* Wac    = (const float*)d_in[8];
    const float* Waw    = (const float*)d_in[9];
    const float* Wv     = (const float*)d_in[10];
    const float* bv     = (const float*)d_in[11];
    float* out = (float*)d_out;

    k_query<<<Bt, 256>>>(hidden, Wh, bh);
    {
        int ntw = Ct * At + 3 * At;
        k_tw<<<(ntw + 255) / 256, 256>>>(Wec);
    }
    k_weff<<<At, 128>>>(Waw, Wac);
    k_patches<<<(Bt * NPATCH * HWt + 255) / 256, 256>>>(asum);
    k_gemm<<<dim3(HWt / 128, At / 128, Bt), 256>>>(cnn, bec, Wv);
    k_reduceE<<<Bt, 256>>>(bv);
    k_gmax<<<1, 32>>>();
    k_softmax<<<Bt, 256>>>(mask, asum, out);
    k_context<<<dim3(Ct, Bt), 128>>>(cnn, out);
}

// round 4
// speedup vs baseline: 1.5730x; 1.5730x over previous
#include <cuda_runtime.h>
#include <cuda_bf16.h>
#include <stdint.h>
#include <math.h>

#define Bt 32
#define Ct 684
#define Ht 16
#define Wt 64
#define HWt 1024
#define HIDt 256
#define At 512
#define NPATCH 121
#define KCOMB 805
#define KP 832
#define NST 26
#define NPOS 32768
#define ALPHA_OFF (Bt*Ct)
#define ASUM_OFF  (Bt*Ct + Bt*HWt)

// smem: 2 stages * 4 subtiles * (128 rows * 80B) = 81920 B
#define ROWB 80
#define SUBT (128*ROWB)
#define STAGE (4*SUBT)
#define SMEM_SZ (2*STAGE)

// ---------------- device scratch ----------------
__device__ __nv_bfloat16 g_Xhi[(size_t)NPOS * KP];   // 54.5 MB [pos][k]
__device__ __nv_bfloat16 g_Xlo[(size_t)NPOS * KP];   // 54.5 MB
__device__ __nv_bfloat16 g_Whi[At * KP];             // [a][k]
__device__ __nv_bfloat16 g_Wlo[At * KP];
__device__ float g_Weff[At * NPATCH];
__device__ float g_query[Bt * At];                   // q + bh + bec folded
__device__ float g_Epart[4 * NPOS];
__device__ float g_E[Bt * HWt];
__device__ float g_bmax[Bt];
__device__ float g_gmax;

// ---------------- helpers ----------------
__device__ __forceinline__ uint32_t smem_u32(const void* p) {
    uint32_t a;
    asm("{ .reg .u64 t; cvta.to.shared.u64 t, %1; cvt.u32.u64 %0, t; }" : "=r"(a) : "l"(p));
    return a;
}
__device__ __forceinline__ void cpa16(uint32_t dst, const void* src) {
    asm volatile("cp.async.cg.shared.global [%0], [%1], 16;" :: "r"(dst), "l"(src));
}
#define LDMX4(r0,r1,r2,r3,addr) \
    asm volatile("ldmatrix.sync.aligned.m8n8.x4.shared.b16 {%0,%1,%2,%3}, [%4];" \
                 : "=r"(r0),"=r"(r1),"=r"(r2),"=r"(r3) : "r"(addr))
#define MMA(d,a,b) \
    asm volatile("mma.sync.aligned.m16n8k16.row.col.f32.bf16.bf16.f32 " \
                 "{%0,%1,%2,%3},{%4,%5,%6,%7},{%8,%9},{%0,%1,%2,%3};" \
                 : "+f"(d[0]),"+f"(d[1]),"+f"(d[2]),"+f"(d[3]) \
                 : "r"(a[0]),"r"(a[1]),"r"(a[2]),"r"(a[3]),"r"(b[0]),"r"(b[1]))

__device__ __forceinline__ void split2(float v0, float v1, __nv_bfloat162& hi, __nv_bfloat162& lo) {
    hi = __floats2bfloat162_rn(v0, v1);
    float2 f = __bfloat1622float2(hi);
    lo = __floats2bfloat162_rn(v0 - f.x, v1 - f.y);
}

// ---------------- prep: query = hidden@Wh^T + bh + bec ----------------
__global__ void k_query(const float* __restrict__ hidden, const float* __restrict__ Wh,
                        const float* __restrict__ bh, const float* __restrict__ bec) {
    int b = blockIdx.x, tid = threadIdx.x;
    __shared__ float h[HIDt];
    if (tid < HIDt) h[tid] = hidden[b * HIDt + tid];
    __syncthreads();
    for (int a = tid; a < At; a += 256) {
        const float* wr = Wh + a * HIDt;
        float s = 0.f;
        #pragma unroll 8
        for (int k = 0; k < HIDt; ++k) s = fmaf(wr[k], h[k], s);
        g_query[b * At + a] = s + bh[a] + bec[a];
    }
}

// ---------------- prep: Weff[a][j] = sum_c Waw[a][c]*Wac[c][j] ----------------
__global__ void k_weff(const float* __restrict__ Waw, const float* __restrict__ Wac) {
    int a = blockIdx.x, j = threadIdx.x;
    if (j >= NPATCH) return;
    float s = 0.f;
    for (int c = 0; c < At; ++c) s = fmaf(Waw[a * At + c], Wac[c * NPATCH + j], s);
    g_Weff[a * NPATCH + j] = s;
}

// ---------------- prep: pack W hi/lo row-major [a][KP] ----------------
__global__ void k_wpack(const float* __restrict__ Wec) {
    __shared__ float sm[32][257];
    const int s = blockIdx.x, ag = blockIdx.y, tid = threadIdx.x;
    for (int kr = 0; kr < 32; ++kr) {
        int a = ag * 256 + tid, k = s * 32 + kr;
        float v = 0.f;
        if (k < Ct) v = Wec[a * Ct + k];
        else if (k < KCOMB) v = g_Weff[a * NPATCH + (k - Ct)];
        sm[kr][tid] = v;
    }
    __syncthreads();
    #pragma unroll
    for (int i = 0; i < 16; ++i) {
        int idx = i * 256 + tid;
        int r = idx >> 4, kp = (idx & 15) * 2;
        __nv_bfloat162 hi, lo;
        split2(sm[kp][r], sm[kp + 1][r], hi, lo);
        size_t off = (size_t)(ag * 256 + r) * KP + s * 32 + kp;
        *(__nv_bfloat162*)(g_Whi + off) = hi;
        *(__nv_bfloat162*)(g_Wlo + off) = lo;
    }
}

// ---------------- prep: pack X hi/lo row-major [pos][KP] (cnn + inline im2col) ----------------
__global__ void k_xprep(const float* __restrict__ cnn, const float* __restrict__ asum) {
    __shared__ float sm[32][257];
    const int s = blockIdx.x, pg = blockIdx.y, tid = threadIdx.x;
    const int b = pg >> 2, posb = (pg & 3) * 256 + tid;
    for (int kr = 0; kr < 32; ++kr) {
        int k = s * 32 + kr;
        float v = 0.f;
        if (k < Ct) {
            v = cnn[(size_t)b * (Ct * HWt) + k * HWt + posb];
        } else if (k < KCOMB) {
            int j = k - Ct;
            int hh = (posb >> 6) + j / 11 - 5;
            int ww = (posb & 63) + j % 11 - 5;
            if (hh >= 0 && hh < Ht && ww >= 0 && ww < Wt) v = asum[b * HWt + hh * Wt + ww];
        }
        sm[kr][tid] = v;
    }
    __syncthreads();
    #pragma unroll
    for (int i = 0; i < 16; ++i) {
        int idx = i * 256 + tid;
        int r = idx >> 4, kp = (idx & 15) * 2;
        __nv_bfloat162 hi, lo;
        split2(sm[kp][r], sm[kp + 1][r], hi, lo);
        size_t off = (size_t)(pg * 256 + r) * KP + s * 32 + kp;
        *(__nv_bfloat162*)(g_Xhi + off) = hi;
        *(__nv_bfloat162*)(g_Xlo + off) = lo;
    }
}

// ---------------- stage loader: 4 subtiles (Xhi,Xlo,Whi,Wlo), 128 rows x 64B each ----------------
__device__ __forceinline__ void stage_load(uint32_t sb, int s, int buf, int pos0, int a0, int tid) {
    const uint32_t tb = sb + buf * STAGE;
    const char* srcs[4] = {
        (const char*)(g_Xhi + (size_t)pos0 * KP + s * 32),
        (const char*)(g_Xlo + (size_t)pos0 * KP + s * 32),
        (const char*)(g_Whi + (size_t)a0  * KP + s * 32),
        (const char*)(g_Wlo + (size_t)a0  * KP + s * 32)
    };
    #pragma unroll
    for (int sub = 0; sub < 4; ++sub) {
        #pragma unroll
        for (int j = 0; j < 2; ++j) {
            int id = j * 256 + tid;          // 512 chunks of 16B
            int row = id >> 2, c = id & 3;
            cpa16(tb + sub * SUBT + row * ROWB + c * 16,
                  srcs[sub] + (size_t)row * (KP * 2) + c * 16);
        }
    }
    asm volatile("cp.async.commit_group;" ::: "memory");
}

// ---------------- main: mma.sync bf16 3-product GEMM + tanh/Wv epilogue ----------------
// CTA: 128 pos x 128 a. 8 warps: wm = w>>1 (4 m-strips of 32), wn = w&1 (2 n-strips of 64).
__global__ __launch_bounds__(256, 1)
void k_mma(const float* __restrict__ Wv) {
    extern __shared__ char dsm[];
    const uint32_t sb = smem_u32(dsm);
    const int tid = threadIdx.x, lane = tid & 31, w = tid >> 5;
    const int wm = w >> 1, wn = w & 1;
    const int pos0 = blockIdx.x * 128, a0 = blockIdx.y * 128, b = pos0 >> 10;

    float acc[2][8][4];
    #pragma unroll
    for (int mt = 0; mt < 2; ++mt)
        #pragma unroll
        for (int nt = 0; nt < 8; ++nt)
            #pragma unroll
            for (int r = 0; r < 4; ++r) acc[mt][nt][r] = 0.f;

    stage_load(sb, 0, 0, pos0, a0, tid);

    for (int s = 0; s < NST; ++s) {
        if (s + 1 < NST) {
            stage_load(sb, s + 1, (s + 1) & 1, pos0, a0, tid);
            asm volatile("cp.async.wait_group 1;" ::: "memory");
        } else {
            asm volatile("cp.async.wait_group 0;" ::: "memory");
        }
        __syncthreads();

        const uint32_t tb = sb + (s & 1) * STAGE;
        const uint32_t xh = tb, xl = tb + SUBT, wh = tb + 2 * SUBT, wl = tb + 3 * SUBT;

        #pragma unroll
        for (int ks = 0; ks < 2; ++ks) {
            uint32_t ahi[2][4], alo[2][4], bhi[8][2], blo[8][2];
            // A fragments (16x16 each): lane&15 = row, lane>>4 selects k-half
            const uint32_t aoff = (wm * 32 + (lane & 15)) * ROWB + ks * 32 + (lane >> 4) * 16;
            #pragma unroll
            for (int mt = 0; mt < 2; ++mt) {
                LDMX4(ahi[mt][0], ahi[mt][1], ahi[mt][2], ahi[mt][3], xh + aoff + mt * 16 * ROWB);
                LDMX4(alo[mt][0], alo[mt][1], alo[mt][2], alo[mt][3], xl + aoff + mt * 16 * ROWB);
            }
            // B fragments: x4 covers n16 x k16. lane group g=lane>>3:
            // g0:(n0-7,k0) g1:(n0-7,k16B) g2:(n8-15,k0) g3:(n8-15,k16B)
            const int g = lane >> 3;
            const uint32_t boff = (wn * 64 + (lane & 7) + (g >> 1) * 8) * ROWB + ks * 32 + (g & 1) * 16;
            #pragma unroll
            for (int np = 0; np < 4; ++np) {
                LDMX4(bhi[np*2][0], bhi[np*2][1], bhi[np*2+1][0], bhi[np*2+1][1], wh + boff + np * 16 * ROWB);
                LDMX4(blo[np*2][0], blo[np*2][1], blo[np*2+1][0], blo[np*2+1][1], wl + boff + np * 16 * ROWB);
            }
            #pragma unroll
            for (int mt = 0; mt < 2; ++mt)
                #pragma unroll
                for (int nt = 0; nt < 8; ++nt) {
                    MMA(acc[mt][nt], ahi[mt], bhi[nt]);
                    MMA(acc[mt][nt], alo[mt], bhi[nt]);
                    MMA(acc[mt][nt], ahi[mt], blo[nt]);
                }
        }
        __syncthreads();
    }

    // epilogue: e[pos] = sum_a Wv[a]*tanh(acc + q[b][a])
    float* qs  = (float*)dsm;          // 128
    float* ws  = qs + 128;             // 128
    float* esm = ws + 128;             // 128*2
    if (tid < 128) {
        qs[tid] = g_query[b * At + a0 + tid];
        ws[tid] = Wv[a0 + tid];
    }
    __syncthreads();

    #pragma unroll
    for (int mt = 0; mt < 2; ++mt) {
        float er0 = 0.f, er1 = 0.f;
        #pragma unroll
        for (int nt = 0; nt < 8; ++nt) {
            int col = wn * 64 + nt * 8 + (lane & 3) * 2;
            float q0 = qs[col], q1 = qs[col + 1];
            float w0 = ws[col], w1 = ws[col + 1];
            er0 = fmaf(w0, tanhf(acc[mt][nt][0] + q0), er0);
            er0 = fmaf(w1, tanhf(acc[mt][nt][1] + q1), er0);
            er1 = fmaf(w0, tanhf(acc[mt][nt][2] + q0), er1);
            er1 = fmaf(w1, tanhf(acc[mt][nt][3] + q1), er1);
        }
        er0 += __shfl_xor_sync(0xffffffffu, er0, 1);
        er0 += __shfl_xor_sync(0xffffffffu, er0, 2);
        er1 += __shfl_xor_sync(0xffffffffu, er1, 1);
        er1 += __shfl_xor_sync(0xffffffffu, er1, 2);
        if ((lane & 3) == 0) {
            int r = wm * 32 + mt * 16 + (lane >> 2);
            esm[r * 2 + wn] = er0;
            esm[(r + 8) * 2 + wn] = er1;
        }
    }
    __syncthreads();
    if (tid < 128)
        g_Epart[blockIdx.y * NPOS + pos0 + tid] = esm[tid * 2] + esm[tid * 2 + 1];
}

// ---------------- tails ----------------
__global__ void k_reduceE(const float* __restrict__ bv) {
    int b = blockIdx.x, tid = threadIdx.x;
    float bvv = bv[0], m = -1e30f;
    for (int p = tid; p < HWt; p += 256) {
        float s = bvv;
        #pragma unroll
        for (int t = 0; t < 4; ++t) s += g_Epart[t * NPOS + b * HWt + p];
        g_E[b * HWt + p] = s;
        m = fmaxf(m, s);
    }
    __shared__ float sm[256];
    sm[tid] = m; __syncthreads();
    for (int s2 = 128; s2 > 0; s2 >>= 1) { if (tid < s2) sm[tid] = fmaxf(sm[tid], sm[tid + s2]); __syncthreads(); }
    if (tid == 0) g_bmax[b] = sm[0];
}

__global__ void k_gmax() {
    float v = g_bmax[threadIdx.x];
    #pragma unroll
    for (int o = 16; o > 0; o >>= 1) v = fmaxf(v, __shfl_xor_sync(0xffffffffu, v, o));
    if (threadIdx.x == 0) g_gmax = v;
}

__global__ void k_softmax(const float* __restrict__ mask, const float* __restrict__ asum,
                          float* __restrict__ out) {
    int b = blockIdx.x, tid = threadIdx.x;
    __shared__ float ex[HWt];
    __shared__ float sm[256];
    float gm = g_gmax, ls = 0.f;
    for (int p = tid; p < HWt; p += 256) {
        float v = expf(g_E[b * HWt + p] - gm) * mask[b * HWt + p];
        ex[p] = v; ls += v;
    }
    sm[tid] = ls; __syncthreads();
    for (int s2 = 128; s2 > 0; s2 >>= 1) { if (tid < s2) sm[tid] += sm[tid + s2]; __syncthreads(); }
    float inv = 1.f / (sm[0] + 1e-10f);
    for (int p = tid; p < HWt; p += 256) {
        float al = ex[p] * inv;
        out[ALPHA_OFF + b * HWt + p] = al;
        out[ASUM_OFF + b * HWt + p] = al + asum[b * HWt + p];
    }
}

__global__ void k_context(const float* __restrict__ cnn, float* __restrict__ out) {
    int c = blockIdx.x, b = blockIdx.y, tid = threadIdx.x;
    const float* f = cnn + (size_t)(b * Ct + c) * HWt;
    const float* al = out + ALPHA_OFF + b * HWt;
    float s = 0.f;
    for (int p = tid; p < HWt; p += 128) s = fmaf(al[p], f[p], s);
    #pragma unroll
    for (int o = 16; o > 0; o >>= 1) s += __shfl_xor_sync(0xffffffffu, s, o);
    __shared__ float sm[4];
    if ((tid & 31) == 0) sm[tid >> 5] = s;
    __syncthreads();
    if (tid == 0) out[b * Ct + c] = sm[0] + sm[1] + sm[2] + sm[3];
}

// ---------------- launch ----------------
extern "C" void kernel_launch(void* const* d_in, const int* in_sizes, int n_in,
                              void* d_out, int out_size) {
    const float* cnn    = (const float*)d_in[0];
    const float* hidden = (const float*)d_in[1];
    const float* asum   = (const float*)d_in[2];
    const float* mask   = (const float*)d_in[3];
    const float* Wh     = (const float*)d_in[4];
    const float* bh     = (const float*)d_in[5];
    const float* Wec    = (const float*)d_in[6];
    const float* bec    = (const float*)d_in[7];
    const float* Wac    = (const float*)d_in[8];
    const float* Waw    = (const float*)d_in[9];
    const float* Wv     = (const float*)d_in[10];
    const float* bv     = (const float*)d_in[11];
    float* out = (float*)d_out;

    cudaFuncSetAttribute(k_mma, cudaFuncAttributeMaxDynamicSharedMemorySize, SMEM_SZ);

    k_query<<<Bt, 256>>>(hidden, Wh, bh, bec);
    k_weff<<<At, 128>>>(Waw, Wac);
    k_wpack<<<dim3(NST, 2), 256>>>(Wec);
    k_xprep<<<dim3(NST, 128), 256>>>(cnn, asum);
    k_mma<<<dim3(NPOS / 128, At / 128), 256, SMEM_SZ>>>(Wv);
    k_reduceE<<<Bt, 256>>>(bv);
    k_gmax<<<1, 32>>>();
    k_softmax<<<Bt, 256>>>(mask, asum, out);
    k_context<<<dim3(Ct, Bt), 128>>>(cnn, out);
}

// round 5
// speedup vs baseline: 1.5997x; 1.0170x over previous
#include <cuda_runtime.h>
#include <cuda_bf16.h>
#include <stdint.h>
#include <math.h>

#define Bt 32
#define Ct 684
#define Ht 16
#define Wt 64
#define HWt 1024
#define HIDt 256
#define At 512
#define NPATCH 121
#define KCOMB 805
#define KP 832
#define NST 26
#define NPOS 32768
#define ALPHA_OFF (Bt*Ct)
#define ASUM_OFF  (Bt*Ct + Bt*HWt)

// stage: Xhi[128*80] Xlo[128*80] Whi[256*80] Wlo[256*80] = 61440 B; 2 stages
#define ROWB 80
#define XSUB (128*ROWB)
#define WSUB (256*ROWB)
#define STAGE (2*XSUB + 2*WSUB)
#define SMEM_SZ (2*STAGE)

// ---------------- device scratch ----------------
__device__ __nv_bfloat16 g_Xhi[(size_t)NPOS * KP];
__device__ __nv_bfloat16 g_Xlo[(size_t)NPOS * KP];
__device__ __nv_bfloat16 g_Whi[At * KP];
__device__ __nv_bfloat16 g_Wlo[At * KP];
__device__ float g_Weff[At * NPATCH];
__device__ float g_query[Bt * At];       // q + bh + bec folded
__device__ float g_Epart[2 * NPOS];
__device__ float g_E[Bt * HWt];
__device__ float g_bmax[Bt];
__device__ float g_gmax;

// ---------------- helpers ----------------
__device__ __forceinline__ uint32_t smem_u32(const void* p) {
    uint32_t a;
    asm("{ .reg .u64 t; cvta.to.shared.u64 t, %1; cvt.u32.u64 %0, t; }" : "=r"(a) : "l"(p));
    return a;
}
__device__ __forceinline__ void cpa16(uint32_t dst, const void* src) {
    asm volatile("cp.async.cg.shared.global [%0], [%1], 16;" :: "r"(dst), "l"(src));
}
#define LDMX4(r0,r1,r2,r3,addr) \
    asm volatile("ldmatrix.sync.aligned.m8n8.x4.shared.b16 {%0,%1,%2,%3}, [%4];" \
                 : "=r"(r0),"=r"(r1),"=r"(r2),"=r"(r3) : "r"(addr))
#define MMA(d,a,b) \
    asm volatile("mma.sync.aligned.m16n8k16.row.col.f32.bf16.bf16.f32 " \
                 "{%0,%1,%2,%3},{%4,%5,%6,%7},{%8,%9},{%0,%1,%2,%3};" \
                 : "+f"(d[0]),"+f"(d[1]),"+f"(d[2]),"+f"(d[3]) \
                 : "r"(a[0]),"r"(a[1]),"r"(a[2]),"r"(a[3]),"r"(b[0]),"r"(b[1]))

__device__ __forceinline__ void split2(float v0, float v1, __nv_bfloat162& hi, __nv_bfloat162& lo) {
    hi = __floats2bfloat162_rn(v0, v1);
    float2 f = __bfloat1622float2(hi);
    lo = __floats2bfloat162_rn(v0 - f.x, v1 - f.y);
}

// ---------------- prep kernels (unchanged from R4) ----------------
__global__ void k_query(const float* __restrict__ hidden, const float* __restrict__ Wh,
                        const float* __restrict__ bh, const float* __restrict__ bec) {
    int b = blockIdx.x, tid = threadIdx.x;
    __shared__ float h[HIDt];
    if (tid < HIDt) h[tid] = hidden[b * HIDt + tid];
    __syncthreads();
    for (int a = tid; a < At; a += 256) {
        const float* wr = Wh + a * HIDt;
        float s = 0.f;
        #pragma unroll 8
        for (int k = 0; k < HIDt; ++k) s = fmaf(wr[k], h[k], s);
        g_query[b * At + a] = s + bh[a] + bec[a];
    }
}

__global__ void k_weff(const float* __restrict__ Waw, const float* __restrict__ Wac) {
    int a = blockIdx.x, j = threadIdx.x;
    if (j >= NPATCH) return;
    float s = 0.f;
    for (int c = 0; c < At; ++c) s = fmaf(Waw[a * At + c], Wac[c * NPATCH + j], s);
    g_Weff[a * NPATCH + j] = s;
}

__global__ void k_wpack(const float* __restrict__ Wec) {
    __shared__ float sm[32][257];
    const int s = blockIdx.x, ag = blockIdx.y, tid = threadIdx.x;
    for (int kr = 0; kr < 32; ++kr) {
        int a = ag * 256 + tid, k = s * 32 + kr;
        float v = 0.f;
        if (k < Ct) v = Wec[a * Ct + k];
        else if (k < KCOMB) v = g_Weff[a * NPATCH + (k - Ct)];
        sm[kr][tid] = v;
    }
    __syncthreads();
    #pragma unroll
    for (int i = 0; i < 16; ++i) {
        int idx = i * 256 + tid;
        int r = idx >> 4, kp = (idx & 15) * 2;
        __nv_bfloat162 hi, lo;
        split2(sm[kp][r], sm[kp + 1][r], hi, lo);
        size_t off = (size_t)(ag * 256 + r) * KP + s * 32 + kp;
        *(__nv_bfloat162*)(g_Whi + off) = hi;
        *(__nv_bfloat162*)(g_Wlo + off) = lo;
    }
}

__global__ void k_xprep(const float* __restrict__ cnn, const float* __restrict__ asum) {
    __shared__ float sm[32][257];
    const int s = blockIdx.x, pg = blockIdx.y, tid = threadIdx.x;
    const int b = pg >> 2, posb = (pg & 3) * 256 + tid;
    for (int kr = 0; kr < 32; ++kr) {
        int k = s * 32 + kr;
        float v = 0.f;
        if (k < Ct) {
            v = cnn[(size_t)b * (Ct * HWt) + k * HWt + posb];
        } else if (k < KCOMB) {
            int j = k - Ct;
            int hh = (posb >> 6) + j / 11 - 5;
            int ww = (posb & 63) + j % 11 - 5;
            if (hh >= 0 && hh < Ht && ww >= 0 && ww < Wt) v = asum[b * HWt + hh * Wt + ww];
        }
        sm[kr][tid] = v;
    }
    __syncthreads();
    #pragma unroll
    for (int i = 0; i < 16; ++i) {
        int idx = i * 256 + tid;
        int r = idx >> 4, kp = (idx & 15) * 2;
        __nv_bfloat162 hi, lo;
        split2(sm[kp][r], sm[kp + 1][r], hi, lo);
        size_t off = (size_t)(pg * 256 + r) * KP + s * 32 + kp;
        *(__nv_bfloat162*)(g_Xhi + off) = hi;
        *(__nv_bfloat162*)(g_Xlo + off) = lo;
    }
}

// ---------------- stage loader: X 2x(128x64B), W 2x(256x64B) ----------------
__device__ __forceinline__ void stage_load(uint32_t sb, int s, int buf, int pos0, int a0, int tid) {
    const uint32_t tb = sb + buf * STAGE;
    const char* xs[2] = {
        (const char*)g_Xhi + ((size_t)pos0 * KP + s * 32) * 2,
        (const char*)g_Xlo + ((size_t)pos0 * KP + s * 32) * 2
    };
    const char* wsrc[2] = {
        (const char*)g_Whi + ((size_t)a0 * KP + s * 32) * 2,
        (const char*)g_Wlo + ((size_t)a0 * KP + s * 32) * 2
    };
    #pragma unroll
    for (int j = 0; j < 4; ++j) {                     // X: 1024 chunks
        int id = j * 256 + tid;
        int sub = id >> 9, rc = id & 511;
        int row = rc >> 2, c = rc & 3;
        cpa16(tb + sub * XSUB + row * ROWB + c * 16,
              xs[sub] + (size_t)row * (KP * 2) + c * 16);
    }
    #pragma unroll
    for (int j = 0; j < 8; ++j) {                     // W: 2048 chunks
        int id = j * 256 + tid;
        int sub = id >> 10, rc = id & 1023;
        int row = rc >> 2, c = rc & 3;
        cpa16(tb + 2 * XSUB + sub * WSUB + row * ROWB + c * 16,
              wsrc[sub] + (size_t)row * (KP * 2) + c * 16);
    }
    asm volatile("cp.async.commit_group;" ::: "memory");
}

// ---------------- main: CTA 128 pos x 256 a, warp tile 64x64 ----------------
__global__ __launch_bounds__(256, 1)
void k_mma(const float* __restrict__ Wv) {
    extern __shared__ char dsm[];
    const uint32_t sb = smem_u32(dsm);
    const int tid = threadIdx.x, lane = tid & 31, w = tid >> 5;
    const int wm = w >> 2, wn = w & 3;
    const int pos0 = blockIdx.x * 128, a0 = blockIdx.y * 256, b = pos0 >> 10;

    float acc[4][8][4];
    #pragma unroll
    for (int mt = 0; mt < 4; ++mt)
        #pragma unroll
        for (int nt = 0; nt < 8; ++nt)
            #pragma unroll
            for (int r = 0; r < 4; ++r) acc[mt][nt][r] = 0.f;

    stage_load(sb, 0, 0, pos0, a0, tid);

    for (int s = 0; s < NST; ++s) {
        if (s + 1 < NST) {
            stage_load(sb, s + 1, (s + 1) & 1, pos0, a0, tid);
            asm volatile("cp.async.wait_group 1;" ::: "memory");
        } else {
            asm volatile("cp.async.wait_group 0;" ::: "memory");
        }
        __syncthreads();

        const uint32_t tb = sb + (s & 1) * STAGE;
        const uint32_t xh = tb, xl = tb + XSUB;
        const uint32_t wh = tb + 2 * XSUB, wl = wh + WSUB;

        #pragma unroll
        for (int ks = 0; ks < 2; ++ks) {
            uint32_t bhi[8][2], blo[8][2];
            const int g = lane >> 3;
            const uint32_t boff = (wn * 64 + (lane & 7) + (g >> 1) * 8) * ROWB
                                + ks * 32 + (g & 1) * 16;
            #pragma unroll
            for (int np = 0; np < 4; ++np) {
                LDMX4(bhi[np*2][0], bhi[np*2][1], bhi[np*2+1][0], bhi[np*2+1][1],
                      wh + boff + np * 16 * ROWB);
                LDMX4(blo[np*2][0], blo[np*2][1], blo[np*2+1][0], blo[np*2+1][1],
                      wl + boff + np * 16 * ROWB);
            }
            const uint32_t aoff = (wm * 64 + (lane & 15)) * ROWB + ks * 32 + (lane >> 4) * 16;
            #pragma unroll
            for (int mt = 0; mt < 4; ++mt) {
                uint32_t ahi[4], alo[4];
                LDMX4(ahi[0], ahi[1], ahi[2], ahi[3], xh + aoff + mt * 16 * ROWB);
                LDMX4(alo[0], alo[1], alo[2], alo[3], xl + aoff + mt * 16 * ROWB);
                #pragma unroll
                for (int nt = 0; nt < 8; ++nt) {
                    MMA(acc[mt][nt], ahi, bhi[nt]);
                    MMA(acc[mt][nt], alo, bhi[nt]);
                    MMA(acc[mt][nt], ahi, blo[nt]);
                }
            }
        }
        __syncthreads();
    }

    // epilogue: e[pos] = sum_a Wv[a]*tanh(acc + q[b][a])
    float* qs  = (float*)dsm;          // 256
    float* ws  = qs + 256;             // 256
    float* esm = ws + 256;             // 128*4
    qs[tid] = g_query[b * At + a0 + tid];
    ws[tid] = Wv[a0 + tid];
    __syncthreads();

    #pragma unroll
    for (int mt = 0; mt < 4; ++mt) {
        float er0 = 0.f, er1 = 0.f;
        #pragma unroll
        for (int nt = 0; nt < 8; ++nt) {
            int col = wn * 64 + nt * 8 + (lane & 3) * 2;
            float q0 = qs[col], q1 = qs[col + 1];
            float w0 = ws[col], w1 = ws[col + 1];
            er0 = fmaf(w0, tanhf(acc[mt][nt][0] + q0), er0);
            er0 = fmaf(w1, tanhf(acc[mt][nt][1] + q1), er0);
            er1 = fmaf(w0, tanhf(acc[mt][nt][2] + q0), er1);
            er1 = fmaf(w1, tanhf(acc[mt][nt][3] + q1), er1);
        }
        er0 += __shfl_xor_sync(0xffffffffu, er0, 1);
        er0 += __shfl_xor_sync(0xffffffffu, er0, 2);
        er1 += __shfl_xor_sync(0xffffffffu, er1, 1);
        er1 += __shfl_xor_sync(0xffffffffu, er1, 2);
        if ((lane & 3) == 0) {
            int r = wm * 64 + mt * 16 + (lane >> 2);
            esm[r * 4 + wn] = er0;
            esm[(r + 8) * 4 + wn] = er1;
        }
    }
    __syncthreads();
    if (tid < 128)
        g_Epart[blockIdx.y * NPOS + pos0 + tid] =
            esm[tid * 4] + esm[tid * 4 + 1] + esm[tid * 4 + 2] + esm[tid * 4 + 3];
}

// ---------------- tails ----------------
__global__ void k_reduceE(const float* __restrict__ bv) {
    int b = blockIdx.x, tid = threadIdx.x;
    float bvv = bv[0], m = -1e30f;
    for (int p = tid; p < HWt; p += 256) {
        float s = bvv + g_Epart[b * HWt + p] + g_Epart[NPOS + b * HWt + p];
        g_E[b * HWt + p] = s;
        m = fmaxf(m, s);
    }
    __shared__ float sm[256];
    sm[tid] = m; __syncthreads();
    for (int s2 = 128; s2 > 0; s2 >>= 1) { if (tid < s2) sm[tid] = fmaxf(sm[tid], sm[tid + s2]); __syncthreads(); }
    if (tid == 0) g_bmax[b] = sm[0];
}

__global__ void k_gmax() {
    float v = g_bmax[threadIdx.x];
    #pragma unroll
    for (int o = 16; o > 0; o >>= 1) v = fmaxf(v, __shfl_xor_sync(0xffffffffu, v, o));
    if (threadIdx.x == 0) g_gmax = v;
}

__global__ void k_softmax(const float* __restrict__ mask, const float* __restrict__ asum,
                          float* __restrict__ out) {
    int b = blockIdx.x, tid = threadIdx.x;
    __shared__ float ex[HWt];
    __shared__ float sm[256];
    float gm = g_gmax, ls = 0.f;
    for (int p = tid; p < HWt; p += 256) {
        float v = expf(g_E[b * HWt + p] - gm) * mask[b * HWt + p];
        ex[p] = v; ls += v;
    }
    sm[tid] = ls; __syncthreads();
    for (int s2 = 128; s2 > 0; s2 >>= 1) { if (tid < s2) sm[tid] += sm[tid + s2]; __syncthreads(); }
    float inv = 1.f / (sm[0] + 1e-10f);
    for (int p = tid; p < HWt; p += 256) {
        float al = ex[p] * inv;
        out[ALPHA_OFF + b * HWt + p] = al;
        out[ASUM_OFF + b * HWt + p] = al + asum[b * HWt + p];
    }
}

__global__ void k_context(const float* __restrict__ cnn, float* __restrict__ out) {
    int c = blockIdx.x, b = blockIdx.y, tid = threadIdx.x;
    const float* f = cnn + (size_t)(b * Ct + c) * HWt;
    const float* al = out + ALPHA_OFF + b * HWt;
    float s = 0.f;
    for (int p = tid; p < HWt; p += 128) s = fmaf(al[p], f[p], s);
    #pragma unroll
    for (int o = 16; o > 0; o >>= 1) s += __shfl_xor_sync(0xffffffffu, s, o);
    __shared__ float sm[4];
    if ((tid & 31) == 0) sm[tid >> 5] = s;
    __syncthreads();
    if (tid == 0) out[b * Ct + c] = sm[0] + sm[1] + sm[2] + sm[3];
}

// ---------------- launch ----------------
extern "C" void kernel_launch(void* const* d_in, const int* in_sizes, int n_in,
                              void* d_out, int out_size) {
    const float* cnn    = (const float*)d_in[0];
    const float* hidden = (const float*)d_in[1];
    const float* asum   = (const float*)d_in[2];
    const float* mask   = (const float*)d_in[3];
    const float* Wh     = (const float*)d_in[4];
    const float* bh     = (const float*)d_in[5];
    const float* Wec    = (const float*)d_in[6];
    const float* bec    = (const float*)d_in[7];
    const float* Wac    = (const float*)d_in[8];
    const float* Waw    = (const float*)d_in[9];
    const float* Wv     = (const float*)d_in[10];
    const float* bv     = (const float*)d_in[11];
    float* out = (float*)d_out;

    cudaFuncSetAttribute(k_mma, cudaFuncAttributeMaxDynamicSharedMemorySize, SMEM_SZ);

    k_query<<<Bt, 256>>>(hidden, Wh, bh, bec);
    k_weff<<<At, 128>>>(Waw, Wac);
    k_wpack<<<dim3(NST, 2), 256>>>(Wec);
    k_xprep<<<dim3(NST, 128), 256>>>(cnn, asum);
    k_mma<<<dim3(NPOS / 128, At / 256), 256, SMEM_SZ>>>(Wv);
    k_reduceE<<<Bt, 256>>>(bv);
    k_gmax<<<1, 32>>>();
    k_softmax<<<Bt, 256>>>(mask, asum, out);
    k_context<<<dim3(Ct, Bt), 128>>>(cnn, out);
}

// round 6
// speedup vs baseline: 1.8879x; 1.1801x over previous
#include <cuda_runtime.h>
#include <cuda_bf16.h>
#include <stdint.h>
#include <math.h>

#define Bt 32
#define Ct 684
#define Ht 16
#define Wt 64
#define HWt 1024
#define HIDt 256
#define At 512
#define NPATCH 121
#define KCOMB 805
#define NST 26
#define NPOS 32768
#define ALPHA_OFF (Bt*Ct)
#define ASUM_OFF  (Bt*Ct + Bt*HWt)

// tiles: X (128 pos x 32 k) hi+lo = 16384 B ; W (256 a x 32 k) hi+lo = 32768 B
#define XT 16384
#define WTILE 32768
#define STB (XT + WTILE)
#define SMEM_SZ (2*STB)
#define NTILE 512     // 256 pos-groups x 2 a-groups

// ---------------- device scratch ----------------
__device__ __align__(1024) unsigned char g_X[(size_t)256 * NST * XT];   // 109 MB
__device__ __align__(1024) unsigned char g_W[(size_t)2 * NST * WTILE];  // 1.7 MB
__device__ float g_Weff[At * NPATCH];
__device__ float g_query[Bt * At];       // q + bh + bec folded
__device__ float g_Epart[2 * NPOS];
__device__ float g_E[Bt * HWt];
__device__ float g_bmax[Bt];
__device__ float g_gmax;

// ---------------- helpers ----------------
__device__ __forceinline__ uint32_t smem_u32(const void* p) {
    uint32_t a;
    asm("{ .reg .u64 t; cvta.to.shared.u64 t, %1; cvt.u32.u64 %0, t; }" : "=r"(a) : "l"(p));
    return a;
}
__device__ __forceinline__ void mb_init(uint32_t a, uint32_t c) {
    asm volatile("mbarrier.init.shared.b64 [%0], %1;" :: "r"(a), "r"(c) : "memory");
}
__device__ __forceinline__ void mb_tx(uint32_t a, uint32_t bytes) {
    asm volatile("mbarrier.arrive.expect_tx.shared.b64 _, [%0], %1;" :: "r"(a), "r"(bytes) : "memory");
}
__device__ __forceinline__ void mb_wait(uint32_t a, uint32_t par) {
    uint32_t d = 0;
    while (!d)
        asm volatile("{ .reg .pred p; mbarrier.try_wait.parity.acquire.cta.shared::cta.b64 p,[%1],%2,0x989680; selp.b32 %0,1,0,p; }"
                     : "=r"(d) : "r"(a), "r"(par) : "memory");
}
__device__ __forceinline__ void blkcp(uint32_t dst, const void* src, uint32_t bytes, uint32_t mbar) {
    asm volatile("cp.async.bulk.shared::cta.global.mbarrier::complete_tx::bytes [%0], [%1], %2, [%3];"
                 :: "r"(dst), "l"(src), "r"(bytes), "r"(mbar) : "memory");
}
#define LDMX4(r0,r1,r2,r3,addr) \
    asm volatile("ldmatrix.sync.aligned.m8n8.x4.shared.b16 {%0,%1,%2,%3}, [%4];" \
                 : "=r"(r0),"=r"(r1),"=r"(r2),"=r"(r3) : "r"(addr))
#define MMA(d,a,b) \
    asm volatile("mma.sync.aligned.m16n8k16.row.col.f32.bf16.bf16.f32 " \
                 "{%0,%1,%2,%3},{%4,%5,%6,%7},{%8,%9},{%0,%1,%2,%3};" \
                 : "+f"(d[0]),"+f"(d[1]),"+f"(d[2]),"+f"(d[3]) \
                 : "r"(a[0]),"r"(a[1]),"r"(a[2]),"r"(a[3]),"r"(b[0]),"r"(b[1]))

__device__ __forceinline__ void splitu(float v0, float v1, uint32_t& h, uint32_t& l) {
    __nv_bfloat162 hb = __floats2bfloat162_rn(v0, v1);
    float2 f = __bfloat1622float2(hb);
    __nv_bfloat162 lb = __floats2bfloat162_rn(v0 - f.x, v1 - f.y);
    h = *(uint32_t*)&hb;
    l = *(uint32_t*)&lb;
}

// ---------------- prep: query = hidden@Wh^T + bh + bec ----------------
__global__ void k_query(const float* __restrict__ hidden, const float* __restrict__ Wh,
                        const float* __restrict__ bh, const float* __restrict__ bec) {
    int b = blockIdx.x, tid = threadIdx.x;
    __shared__ float h[HIDt];
    if (tid < HIDt) h[tid] = hidden[b * HIDt + tid];
    __syncthreads();
    for (int a = tid; a < At; a += 256) {
        const float* wr = Wh + a * HIDt;
        float s = 0.f;
        #pragma unroll 8
        for (int k = 0; k < HIDt; ++k) s = fmaf(wr[k], h[k], s);
        g_query[b * At + a] = s + bh[a] + bec[a];
    }
}

// ---------------- prep: Weff[a][j] = sum_c Waw[a][c]*Wac[c][j] ----------------
__global__ void k_weff(const float* __restrict__ Waw, const float* __restrict__ Wac) {
    int a = blockIdx.x, j = threadIdx.x;
    if (j >= NPATCH) return;
    float s = 0.f;
    for (int c = 0; c < At; ++c) s = fmaf(Waw[a * At + c], Wac[c * NPATCH + j], s);
    g_Weff[a * NPATCH + j] = s;
}

// ---------------- prep: W tiles [ag][s] 256a x 32k, swizzled hi/lo ----------------
__global__ void k_wpack(const float* __restrict__ Wec) {
    __shared__ float sm[32][257];
    const int s = blockIdx.x, ag = blockIdx.y, tid = threadIdx.x;
    #pragma unroll 4
    for (int i = 0; i < 32; ++i) {
        int idx = i * 256 + tid;
        int kl = idx & 31, a = idx >> 5;
        int k = s * 32 + kl, aa = ag * 256 + a;
        float v = 0.f;
        if (k < Ct) v = Wec[aa * Ct + k];
        else if (k < KCOMB) v = g_Weff[aa * NPATCH + (k - Ct)];
        sm[kl][a] = v;
    }
    __syncthreads();
    unsigned char* tile = g_W + ((size_t)(ag * NST + s) << 15);
    #pragma unroll
    for (int i = 0; i < 4; ++i) {
        int idx = i * 256 + tid;
        int row = idx >> 2, c = idx & 3;
        uint32_t hv[4], lv[4];
        #pragma unroll
        for (int j = 0; j < 4; ++j)
            splitu(sm[c * 8 + 2 * j][row], sm[c * 8 + 2 * j + 1][row], hv[j], lv[j]);
        uint32_t off = row * 64 + ((c ^ ((row >> 1) & 3)) << 4);
        *(uint4*)(tile + off) = make_uint4(hv[0], hv[1], hv[2], hv[3]);
        *(uint4*)(tile + 16384 + off) = make_uint4(lv[0], lv[1], lv[2], lv[3]);
    }
}

// ---------------- prep: X tiles [pg][s] 128pos x 32k, swizzled hi/lo ----------------
__global__ void k_xprep(const float* __restrict__ cnn, const float* __restrict__ asum) {
    __shared__ float sm[32][129];
    const int s = blockIdx.x, pg = blockIdx.y, tid = threadIdx.x;
    const int b = pg >> 3;
    #pragma unroll
    for (int i = 0; i < 16; ++i) {
        int idx = i * 256 + tid;
        int kr = idx >> 7, p = idx & 127;
        int posb = (pg & 7) * 128 + p;
        int k = s * 32 + kr;
        float v = 0.f;
        if (k < Ct) {
            v = cnn[(size_t)b * (Ct * HWt) + k * HWt + posb];
        } else if (k < KCOMB) {
            int j = k - Ct;
            int hh = (posb >> 6) + j / 11 - 5;
            int ww = (posb & 63) + j % 11 - 5;
            if (hh >= 0 && hh < Ht && ww >= 0 && ww < Wt) v = asum[b * HWt + hh * Wt + ww];
        }
        sm[kr][p] = v;
    }
    __syncthreads();
    unsigned char* tile = g_X + ((size_t)(pg * NST + s) << 14);
    #pragma unroll
    for (int i = 0; i < 2; ++i) {
        int idx = i * 256 + tid;
        int row = idx >> 2, c = idx & 3;
        uint32_t hv[4], lv[4];
        #pragma unroll
        for (int j = 0; j < 4; ++j)
            splitu(sm[c * 8 + 2 * j][row], sm[c * 8 + 2 * j + 1][row], hv[j], lv[j]);
        uint32_t off = row * 64 + ((c ^ ((row >> 1) & 3)) << 4);
        *(uint4*)(tile + off) = make_uint4(hv[0], hv[1], hv[2], hv[3]);
        *(uint4*)(tile + 8192 + off) = make_uint4(lv[0], lv[1], lv[2], lv[3]);
    }
}

// ---------------- main: persistent, CTA tile 128 pos x 256 a, bulk-copy pipeline ----------------
__global__ __launch_bounds__(256, 1)
void k_mma(const float* __restrict__ Wv) {
    extern __shared__ char dsm[];
    __shared__ float qs[256], ws[256], esm[512];
    __shared__ __align__(8) uint64_t mbars[2];
    const uint32_t sb = smem_u32(dsm);
    const uint32_t mb0 = smem_u32(&mbars[0]);
    const int tid = threadIdx.x, lane = tid & 31, w = tid >> 5;
    const int wm = w >> 2, wn = w & 3;

    if (tid == 0) { mb_init(mb0, 1); mb_init(mb0 + 8, 1); }
    __syncthreads();

    uint32_t gsc = 0;
    for (int tile = blockIdx.x; tile < NTILE; tile += 148) {
        const int bx = tile & 255, by = tile >> 8;
        const int pos0 = bx * 128, a0 = by * 256, b = bx >> 3;
        const unsigned char* xsrc = g_X + ((size_t)(bx * NST) << 14);
        const unsigned char* wsrc = g_W + ((size_t)(by * NST) << 15);

        float acc[4][8][4];
        #pragma unroll
        for (int mt = 0; mt < 4; ++mt)
            #pragma unroll
            for (int nt = 0; nt < 8; ++nt)
                #pragma unroll
                for (int r = 0; r < 4; ++r) acc[mt][nt][r] = 0.f;

        if (tid == 0) {
            uint32_t bar = mb0 + (gsc & 1) * 8;
            mb_tx(bar, STB);
            blkcp(sb + (gsc & 1) * STB, xsrc, XT, bar);
            blkcp(sb + (gsc & 1) * STB + XT, wsrc, WTILE, bar);
        }

        for (int s = 0; s < NST; ++s, ++gsc) {
            if (s + 1 < NST && tid == 0) {
                uint32_t nb = (gsc + 1) & 1;
                uint32_t bar = mb0 + nb * 8;
                mb_tx(bar, STB);
                blkcp(sb + nb * STB, xsrc + (size_t)(s + 1) * XT, XT, bar);
                blkcp(sb + nb * STB + XT, wsrc + (size_t)(s + 1) * WTILE, WTILE, bar);
            }
            mb_wait(mb0 + (gsc & 1) * 8, (gsc >> 1) & 1);

            const uint32_t tb = sb + (gsc & 1) * STB;
            const uint32_t xh = tb, xl = tb + 8192;
            const uint32_t wh = tb + XT, wl = wh + 16384;

            #pragma unroll
            for (int ks = 0; ks < 2; ++ks) {
                uint32_t bhi[8][2], blo[8][2];
                const int browb = wn * 64 + (lane & 7) + ((lane >> 4) & 1) * 8;
                const int bc = 2 * ks + ((lane >> 3) & 1);
                #pragma unroll
                for (int np = 0; np < 4; ++np) {
                    int r = browb + np * 16;
                    uint32_t boff = r * 64 + ((bc ^ ((r >> 1) & 3)) << 4);
                    LDMX4(bhi[np*2][0], bhi[np*2][1], bhi[np*2+1][0], bhi[np*2+1][1], wh + boff);
                    LDMX4(blo[np*2][0], blo[np*2][1], blo[np*2+1][0], blo[np*2+1][1], wl + boff);
                }
                const int arow = wm * 64 + (lane & 15);
                const int ac = 2 * ks + (lane >> 4);
                #pragma unroll
                for (int mt = 0; mt < 4; ++mt) {
                    int r = arow + mt * 16;
                    uint32_t aoff = r * 64 + ((ac ^ ((r >> 1) & 3)) << 4);
                    uint32_t ahi[4], alo[4];
                    LDMX4(ahi[0], ahi[1], ahi[2], ahi[3], xh + aoff);
                    LDMX4(alo[0], alo[1], alo[2], alo[3], xl + aoff);
                    #pragma unroll
                    for (int nt = 0; nt < 8; ++nt) {
                        MMA(acc[mt][nt], ahi, bhi[nt]);
                        MMA(acc[mt][nt], alo, bhi[nt]);
                        MMA(acc[mt][nt], ahi, blo[nt]);
                    }
                }
            }
            __syncthreads();
        }

        // epilogue: e[pos] = sum_a Wv[a]*tanh(acc + q[b][a])
        qs[tid] = g_query[b * At + a0 + tid];
        ws[tid] = Wv[a0 + tid];
        __syncthreads();

        #pragma unroll
        for (int mt = 0; mt < 4; ++mt) {
            float er0 = 0.f, er1 = 0.f;
            #pragma unroll
            for (int nt = 0; nt < 8; ++nt) {
                int col = wn * 64 + nt * 8 + (lane & 3) * 2;
                float q0 = qs[col], q1 = qs[col + 1];
                float w0 = ws[col], w1 = ws[col + 1];
                er0 = fmaf(w0, tanhf(acc[mt][nt][0] + q0), er0);
                er0 = fmaf(w1, tanhf(acc[mt][nt][1] + q1), er0);
                er1 = fmaf(w0, tanhf(acc[mt][nt][2] + q0), er1);
                er1 = fmaf(w1, tanhf(acc[mt][nt][3] + q1), er1);
            }
            er0 += __shfl_xor_sync(0xffffffffu, er0, 1);
            er0 += __shfl_xor_sync(0xffffffffu, er0, 2);
            er1 += __shfl_xor_sync(0xffffffffu, er1, 1);
            er1 += __shfl_xor_sync(0xffffffffu, er1, 2);
            if ((lane & 3) == 0) {
                int r = wm * 64 + mt * 16 + (lane >> 2);
                esm[r * 4 + wn] = er0;
                esm[(r + 8) * 4 + wn] = er1;
            }
        }
        __syncthreads();
        if (tid < 128)
            g_Epart[by * NPOS + pos0 + tid] =
                esm[tid * 4] + esm[tid * 4 + 1] + esm[tid * 4 + 2] + esm[tid * 4 + 3];
        __syncthreads();
    }
}

// ---------------- tails ----------------
__global__ void k_reduceE(const float* __restrict__ bv) {
    int b = blockIdx.x, tid = threadIdx.x;
    float bvv = bv[0], m = -1e30f;
    for (int p = tid; p < HWt; p += 256) {
        float s = bvv + g_Epart[b * HWt + p] + g_Epart[NPOS + b * HWt + p];
        g_E[b * HWt + p] = s;
        m = fmaxf(m, s);
    }
    __shared__ float sm[256];
    sm[tid] = m; __syncthreads();
    for (int s2 = 128; s2 > 0; s2 >>= 1) { if (tid < s2) sm[tid] = fmaxf(sm[tid], sm[tid + s2]); __syncthreads(); }
    if (tid == 0) g_bmax[b] = sm[0];
}

__global__ void k_gmax() {
    float v = g_bmax[threadIdx.x];
    #pragma unroll
    for (int o = 16; o > 0; o >>= 1) v = fmaxf(v, __shfl_xor_sync(0xffffffffu, v, o));
    if (threadIdx.x == 0) g_gmax = v;
}

__global__ void k_softmax(const float* __restrict__ mask, const float* __restrict__ asum,
                          float* __restrict__ out) {
    int b = blockIdx.x, tid = threadIdx.x;
    __shared__ float ex[HWt];
    __shared__ float sm[256];
    float gm = g_gmax, ls = 0.f;
    for (int p = tid; p < HWt; p += 256) {
        float v = expf(g_E[b * HWt + p] - gm) * mask[b * HWt + p];
        ex[p] = v; ls += v;
    }
    sm[tid] = ls; __syncthreads();
    for (int s2 = 128; s2 > 0; s2 >>= 1) { if (tid < s2) sm[tid] += sm[tid + s2]; __syncthreads(); }
    float inv = 1.f / (sm[0] + 1e-10f);
    for (int p = tid; p < HWt; p += 256) {
        float al = ex[p] * inv;
        out[ALPHA_OFF + b * HWt + p] = al;
        out[ASUM_OFF + b * HWt + p] = al + asum[b * HWt + p];
    }
}

__global__ void k_context(const float* __restrict__ cnn, float* __restrict__ out) {
    int c = blockIdx.x, b = blockIdx.y, tid = threadIdx.x;
    const float* f = cnn + (size_t)(b * Ct + c) * HWt;
    const float* al = out + ALPHA_OFF + b * HWt;
    float s = 0.f;
    for (int p = tid; p < HWt; p += 128) s = fmaf(al[p], f[p], s);
    #pragma unroll
    for (int o = 16; o > 0; o >>= 1) s += __shfl_xor_sync(0xffffffffu, s, o);
    __shared__ float sm[4];
    if ((tid & 31) == 0) sm[tid >> 5] = s;
    __syncthreads();
    if (tid == 0) out[b * Ct + c] = sm[0] + sm[1] + sm[2] + sm[3];
}

// ---------------- launch ----------------
extern "C" void kernel_launch(void* const* d_in, const int* in_sizes, int n_in,
                              void* d_out, int out_size) {
    const float* cnn    = (const float*)d_in[0];
    const float* hidden = (const float*)d_in[1];
    const float* asum   = (const float*)d_in[2];
    const float* mask   = (const float*)d_in[3];
    const float* Wh     = (const float*)d_in[4];
    const float* bh     = (const float*)d_in[5];
    const float* Wec    = (const float*)d_in[6];
    const float* bec    = (const float*)d_in[7];
    const float* Wac    = (const float*)d_in[8];
    const float* Waw    = (const float*)d_in[9];
    const float* Wv     = (const float*)d_in[10];
    const float* bv     = (const float*)d_in[11];
    float* out = (float*)d_out;

    cudaFuncSetAttribute(k_mma, cudaFuncAttributeMaxDynamicSharedMemorySize, SMEM_SZ);

    k_query<<<Bt, 256>>>(hidden, Wh, bh, bec);
    k_weff<<<At, 128>>>(Waw, Wac);
    k_wpack<<<dim3(NST, 2), 256>>>(Wec);
    k_xprep<<<dim3(NST, 256), 256>>>(cnn, asum);
    k_mma<<<148, 256, SMEM_SZ>>>(Wv);
    k_reduceE<<<Bt, 256>>>(bv);
    k_gmax<<<1, 32>>>();
    k_softmax<<<Bt, 256>>>(mask, asum, out);
    k_context<<<dim3(Ct, Bt), 128>>>(cnn, out);
}

// round 7
// speedup vs baseline: 2.3421x; 1.2406x over previous
#include <cuda_runtime.h>
#include <cuda_fp16.h>
#include <stdint.h>
#include <math.h>

#define Bt 32
#define Ct 684
#define Ht 16
#define Wt 64
#define HWt 1024
#define HIDt 256
#define At 512
#define NPATCH 121
#define KCOMB 805
#define NST 26
#define NPOS 32768
#define ALPHA_OFF (Bt*Ct)
#define ASUM_OFF  (Bt*Ct + Bt*HWt)

// tiles: X (128 pos x 32 k) fp16 = 8192 B ; W (256 a x 32 k) fp16 = 16384 B
#define XT 8192
#define WT 16384
#define STB (XT + WT)
#define NSLOT 4
#define SMEM_SZ (NSLOT*STB)
#define NTILE 512     // 256 pos-groups x 2 a-groups

// ---------------- device scratch ----------------
__device__ __align__(1024) unsigned char g_X[(size_t)256 * NST * XT];   // 54.5 MB
__device__ __align__(1024) unsigned char g_W[(size_t)2 * NST * WT];     // 852 KB
__device__ float g_Weff[At * NPATCH];
__device__ float g_query[Bt * At];       // q + bh + bec folded
__device__ float g_Epart[2 * NPOS];
__device__ float g_E[Bt * HWt];
__device__ float g_bmax[Bt];
__device__ float g_gmax;

// ---------------- helpers ----------------
__device__ __forceinline__ uint32_t smem_u32(const void* p) {
    uint32_t a;
    asm("{ .reg .u64 t; cvta.to.shared.u64 t, %1; cvt.u32.u64 %0, t; }" : "=r"(a) : "l"(p));
    return a;
}
__device__ __forceinline__ void mb_init(uint32_t a, uint32_t c) {
    asm volatile("mbarrier.init.shared.b64 [%0], %1;" :: "r"(a), "r"(c) : "memory");
}
__device__ __forceinline__ void mb_arrive(uint32_t a) {
    asm volatile("mbarrier.arrive.shared.b64 _, [%0];" :: "r"(a) : "memory");
}
__device__ __forceinline__ void mb_tx(uint32_t a, uint32_t bytes) {
    asm volatile("mbarrier.arrive.expect_tx.shared.b64 _, [%0], %1;" :: "r"(a), "r"(bytes) : "memory");
}
__device__ __forceinline__ void mb_wait(uint32_t a, uint32_t par) {
    uint32_t d = 0;
    while (!d)
        asm volatile("{ .reg .pred p; mbarrier.try_wait.parity.acquire.cta.shared::cta.b64 p,[%1],%2,0x989680; selp.b32 %0,1,0,p; }"
                     : "=r"(d) : "r"(a), "r"(par) : "memory");
}
__device__ __forceinline__ void blkcp(uint32_t dst, const void* src, uint32_t bytes, uint32_t mbar) {
    asm volatile("cp.async.bulk.shared::cta.global.mbarrier::complete_tx::bytes [%0], [%1], %2, [%3];"
                 :: "r"(dst), "l"(src), "r"(bytes), "r"(mbar) : "memory");
}
#define LDMX4(r0,r1,r2,r3,addr) \
    asm volatile("ldmatrix.sync.aligned.m8n8.x4.shared.b16 {%0,%1,%2,%3}, [%4];" \
                 : "=r"(r0),"=r"(r1),"=r"(r2),"=r"(r3) : "r"(addr))
#define MMA(d,a,b) \
    asm volatile("mma.sync.aligned.m16n8k16.row.col.f32.f16.f16.f32 " \
                 "{%0,%1,%2,%3},{%4,%5,%6,%7},{%8,%9},{%0,%1,%2,%3};" \
                 : "+f"(d[0]),"+f"(d[1]),"+f"(d[2]),"+f"(d[3]) \
                 : "r"(a[0]),"r"(a[1]),"r"(a[2]),"r"(a[3]),"r"(b[0]),"r"(b[1]))

__device__ __forceinline__ uint32_t h2u(float v0, float v1) {
    __half2 h = __floats2half2_rn(v0, v1);
    return *(uint32_t*)&h;
}

// ---------------- prep: query = hidden@Wh^T + bh + bec ----------------
__global__ void k_query(const float* __restrict__ hidden, const float* __restrict__ Wh,
                        const float* __restrict__ bh, const float* __restrict__ bec) {
    int b = blockIdx.x, tid = threadIdx.x;
    __shared__ float h[HIDt];
    if (tid < HIDt) h[tid] = hidden[b * HIDt + tid];
    __syncthreads();
    for (int a = tid; a < At; a += 256) {
        const float* wr = Wh + a * HIDt;
        float s = 0.f;
        #pragma unroll 8
        for (int k = 0; k < HIDt; ++k) s = fmaf(wr[k], h[k], s);
        g_query[b * At + a] = s + bh[a] + bec[a];
    }
}

// ---------------- prep: Weff[a][j] = sum_c Waw[a][c]*Wac[c][j] ----------------
__global__ void k_weff(const float* __restrict__ Waw, const float* __restrict__ Wac) {
    int a = blockIdx.x, j = threadIdx.x;
    if (j >= NPATCH) return;
    float s = 0.f;
    for (int c = 0; c < At; ++c) s = fmaf(Waw[a * At + c], Wac[c * NPATCH + j], s);
    g_Weff[a * NPATCH + j] = s;
}

// ---------------- prep: W tiles [ag][s] 256a x 32k fp16, swizzled ----------------
__global__ void k_wpack(const float* __restrict__ Wec) {
    __shared__ float sm[32][257];
    const int s = blockIdx.x, ag = blockIdx.y, tid = threadIdx.x;
    #pragma unroll 4
    for (int i = 0; i < 32; ++i) {
        int idx = i * 256 + tid;
        int kl = idx & 31, a = idx >> 5;
        int k = s * 32 + kl, aa = ag * 256 + a;
        float v = 0.f;
        if (k < Ct) v = Wec[aa * Ct + k];
        else if (k < KCOMB) v = g_Weff[aa * NPATCH + (k - Ct)];
        sm[kl][a] = v;
    }
    __syncthreads();
    unsigned char* tile = g_W + ((size_t)(ag * NST + s) << 14);
    #pragma unroll
    for (int i = 0; i < 4; ++i) {
        int idx = i * 256 + tid;
        int row = idx >> 2, c = idx & 3;
        uint32_t hv[4];
        #pragma unroll
        for (int j = 0; j < 4; ++j)
            hv[j] = h2u(sm[c * 8 + 2 * j][row], sm[c * 8 + 2 * j + 1][row]);
        uint32_t off = row * 64 + ((c ^ ((row >> 1) & 3)) << 4);
        *(uint4*)(tile + off) = make_uint4(hv[0], hv[1], hv[2], hv[3]);
    }
}

// ---------------- prep: X tiles [pg][s] 128pos x 32k fp16, swizzled ----------------
__global__ void k_xprep(const float* __restrict__ cnn, const float* __restrict__ asum) {
    __shared__ float sm[32][129];
    const int s = blockIdx.x, pg = blockIdx.y, tid = threadIdx.x;
    const int b = pg >> 3;
    #pragma unroll
    for (int i = 0; i < 16; ++i) {
        int idx = i * 256 + tid;
        int kr = idx >> 7, p = idx & 127;
        int posb = (pg & 7) * 128 + p;
        int k = s * 32 + kr;
        float v = 0.f;
        if (k < Ct) {
            v = cnn[(size_t)b * (Ct * HWt) + k * HWt + posb];
        } else if (k < KCOMB) {
            int j = k - Ct;
            int hh = (posb >> 6) + j / 11 - 5;
            int ww = (posb & 63) + j % 11 - 5;
            if (hh >= 0 && hh < Ht && ww >= 0 && ww < Wt) v = asum[b * HWt + hh * Wt + ww];
        }
        sm[kr][p] = v;
    }
    __syncthreads();
    unsigned char* tile = g_X + ((size_t)(pg * NST + s) << 13);
    {
        int row = tid >> 1, c = (tid & 1) * 2;   // 256 threads: 2 chunks each (c, c+? no: c in {0,2})
        #pragma unroll
        for (int cc = 0; cc < 2; ++cc) {
            int ch = c + cc;
            uint32_t hv[4];
            #pragma unroll
            for (int j = 0; j < 4; ++j)
                hv[j] = h2u(sm[ch * 8 + 2 * j][row], sm[ch * 8 + 2 * j + 1][row]);
            uint32_t off = row * 64 + ((ch ^ ((row >> 1) & 3)) << 4);
            *(uint4*)(tile + off) = make_uint4(hv[0], hv[1], hv[2], hv[3]);
        }
    }
}

// ---------------- main: persistent, 4-deep bulk pipeline, 128 pos x 256 a ----------------
__global__ __launch_bounds__(256, 1)
void k_mma(const float* __restrict__ Wv) {
    extern __shared__ char dsm[];
    __shared__ float qs[256], ws[256], esm[512];
    __shared__ __align__(8) uint64_t mbars[2 * NSLOT];   // full[0..3], empty[4..7]
    const uint32_t sb = smem_u32(dsm);
    const uint32_t mbF = smem_u32(&mbars[0]);
    const uint32_t mbE = mbF + 8 * NSLOT;
    const int tid = threadIdx.x, lane = tid & 31, w = tid >> 5;
    const int wm = w >> 2, wn = w & 3;

    if (tid == 0)
        for (int i = 0; i < NSLOT; ++i) { mb_init(mbF + 8 * i, 1); mb_init(mbE + 8 * i, 1); }
    __syncthreads();

    int tiles[4], ntiles = 0;
    for (int t = blockIdx.x; t < NTILE; t += 148) tiles[ntiles++] = t;
    const int total = ntiles * NST;

    // producer issue (tid 0 only)
    auto issue = [&](int gs) {
        int ti = gs / NST, s = gs - ti * NST;
        int tile = tiles[ti];
        int bx = tile & 255, by = tile >> 8;
        int slot = gs & (NSLOT - 1), u = gs >> 2;
        mb_wait(mbE + 8 * slot, 1 ^ (u & 1));
        uint32_t fb = mbF + 8 * slot;
        mb_tx(fb, STB);
        blkcp(sb + slot * STB, g_X + ((size_t)(bx * NST + s) << 13), XT, fb);
        blkcp(sb + slot * STB + XT, g_W + ((size_t)(by * NST + s) << 14), WT, fb);
    };

    if (tid == 0)
        for (int gs = 0; gs < 3 && gs < total; ++gs) issue(gs);

    int gs = 0;
    for (int ti = 0; ti < ntiles; ++ti) {
        const int tile = tiles[ti];
        const int bx = tile & 255, by = tile >> 8;
        const int pos0 = bx * 128, a0 = by * 256, b = bx >> 3;

        float acc[4][8][4];
        #pragma unroll
        for (int mt = 0; mt < 4; ++mt)
            #pragma unroll
            for (int nt = 0; nt < 8; ++nt)
                #pragma unroll
                for (int r = 0; r < 4; ++r) acc[mt][nt][r] = 0.f;

        for (int s = 0; s < NST; ++s, ++gs) {
            if (tid == 0 && gs + 3 < total) issue(gs + 3);
            const int slot = gs & (NSLOT - 1), u = gs >> 2;
            mb_wait(mbF + 8 * slot, u & 1);

            const uint32_t xb = sb + slot * STB;
            const uint32_t wb = xb + XT;

            #pragma unroll
            for (int ks = 0; ks < 2; ++ks) {
                uint32_t bf[8][2];
                const int browb = wn * 64 + (lane & 7) + ((lane >> 4) & 1) * 8;
                const int bc = 2 * ks + ((lane >> 3) & 1);
                #pragma unroll
                for (int np = 0; np < 4; ++np) {
                    int r = browb + np * 16;
                    uint32_t boff = r * 64 + ((bc ^ ((r >> 1) & 3)) << 4);
                    LDMX4(bf[np*2][0], bf[np*2][1], bf[np*2+1][0], bf[np*2+1][1], wb + boff);
                }
                const int arow = wm * 64 + (lane & 15);
                const int ac = 2 * ks + (lane >> 4);
                #pragma unroll
                for (int mt = 0; mt < 4; ++mt) {
                    int r = arow + mt * 16;
                    uint32_t aoff = r * 64 + ((ac ^ ((r >> 1) & 3)) << 4);
                    uint32_t af[4];
                    LDMX4(af[0], af[1], af[2], af[3], xb + aoff);
                    #pragma unroll
                    for (int nt = 0; nt < 8; ++nt)
                        MMA(acc[mt][nt], af, bf[nt]);
                }
            }
            __syncthreads();
            if (tid == 0) mb_arrive(mbE + 8 * slot);
        }

        // epilogue: e[pos] = sum_a Wv[a]*tanh(acc + q[b][a])
        qs[tid] = g_query[b * At + a0 + tid];
        ws[tid] = Wv[a0 + tid];
        __syncthreads();

        #pragma unroll
        for (int mt = 0; mt < 4; ++mt) {
            float er0 = 0.f, er1 = 0.f;
            #pragma unroll
            for (int nt = 0; nt < 8; ++nt) {
                int col = wn * 64 + nt * 8 + (lane & 3) * 2;
                float q0 = qs[col], q1 = qs[col + 1];
                float w0 = ws[col], w1 = ws[col + 1];
                er0 = fmaf(w0, tanhf(acc[mt][nt][0] + q0), er0);
                er0 = fmaf(w1, tanhf(acc[mt][nt][1] + q1), er0);
                er1 = fmaf(w0, tanhf(acc[mt][nt][2] + q0), er1);
                er1 = fmaf(w1, tanhf(acc[mt][nt][3] + q1), er1);
            }
            er0 += __shfl_xor_sync(0xffffffffu, er0, 1);
            er0 += __shfl_xor_sync(0xffffffffu, er0, 2);
            er1 += __shfl_xor_sync(0xffffffffu, er1, 1);
            er1 += __shfl_xor_sync(0xffffffffu, er1, 2);
            if ((lane & 3) == 0) {
                int r = wm * 64 + mt * 16 + (lane >> 2);
                esm[r * 4 + wn] = er0;
                esm[(r + 8) * 4 + wn] = er1;
            }
        }
        __syncthreads();
        if (tid < 128)
            g_Epart[by * NPOS + pos0 + tid] =
                esm[tid * 4] + esm[tid * 4 + 1] + esm[tid * 4 + 2] + esm[tid * 4 + 3];
        __syncthreads();
    }
}

// ---------------- tails ----------------
__global__ void k_reduceE(const float* __restrict__ bv) {
    int b = blockIdx.x, tid = threadIdx.x;
    float bvv = bv[0], m = -1e30f;
    for (int p = tid; p < HWt; p += 256) {
        float s = bvv + g_Epart[b * HWt + p] + g_Epart[NPOS + b * HWt + p];
        g_E[b * HWt + p] = s;
        m = fmaxf(m, s);
    }
    __shared__ float sm[256];
    sm[tid] = m; __syncthreads();
    for (int s2 = 128; s2 > 0; s2 >>= 1) { if (tid < s2) sm[tid] = fmaxf(sm[tid], sm[tid + s2]); __syncthreads(); }
    if (tid == 0) g_bmax[b] = sm[0];
}

__global__ void k_gmax() {
    float v = g_bmax[threadIdx.x];
    #pragma unroll
    for (int o = 16; o > 0; o >>= 1) v = fmaxf(v, __shfl_xor_sync(0xffffffffu, v, o));
    if (threadIdx.x == 0) g_gmax = v;
}

__global__ void k_softmax(const float* __restrict__ mask, const float* __restrict__ asum,
                          float* __restrict__ out) {
    int b = blockIdx.x, tid = threadIdx.x;
    __shared__ float ex[HWt];
    __shared__ float sm[256];
    float gm = g_gmax, ls = 0.f;
    for (int p = tid; p < HWt; p += 256) {
        float v = expf(g_E[b * HWt + p] - gm) * mask[b * HWt + p];
        ex[p] = v; ls += v;
    }
    sm[tid] = ls; __syncthreads();
    for (int s2 = 128; s2 > 0; s2 >>= 1) { if (tid < s2) sm[tid] += sm[tid + s2]; __syncthreads(); }
    float inv = 1.f / (sm[0] + 1e-10f);
    for (int p = tid; p < HWt; p += 256) {
        float al = ex[p] * inv;
        out[ALPHA_OFF + b * HWt + p] = al;
        out[ASUM_OFF + b * HWt + p] = al + asum[b * HWt + p];
    }
}

__global__ void k_context(const float* __restrict__ cnn, float* __restrict__ out) {
    int c = blockIdx.x, b = blockIdx.y, tid = threadIdx.x;
    const float* f = cnn + (size_t)(b * Ct + c) * HWt;
    const float* al = out + ALPHA_OFF + b * HWt;
    float s = 0.f;
    for (int p = tid; p < HWt; p += 128) s = fmaf(al[p], f[p], s);
    #pragma unroll
    for (int o = 16; o > 0; o >>= 1) s += __shfl_xor_sync(0xffffffffu, s, o);
    __shared__ float sm[4];
    if ((tid & 31) == 0) sm[tid >> 5] = s;
    __syncthreads();
    if (tid == 0) out[b * Ct + c] = sm[0] + sm[1] + sm[2] + sm[3];
}

// ---------------- launch ----------------
extern "C" void kernel_launch(void* const* d_in, const int* in_sizes, int n_in,
                              void* d_out, int out_size) {
    const float* cnn    = (const float*)d_in[0];
    const float* hidden = (const float*)d_in[1];
    const float* asum   = (const float*)d_in[2];
    const float* mask   = (const float*)d_in[3];
    const float* Wh     = (const float*)d_in[4];
    const float* bh     = (const float*)d_in[5];
    const float* Wec    = (const float*)d_in[6];
    const float* bec    = (const float*)d_in[7];
    const float* Wac    = (const float*)d_in[8];
    const float* Waw    = (const float*)d_in[9];
    const float* Wv     = (const float*)d_in[10];
    const float* bv     = (const float*)d_in[11];
    float* out = (float*)d_out;

    cudaFuncSetAttribute(k_mma, cudaFuncAttributeMaxDynamicSharedMemorySize, SMEM_SZ);

    k_query<<<Bt, 256>>>(hidden, Wh, bh, bec);
    k_weff<<<At, 128>>>(Waw, Wac);
    k_wpack<<<dim3(NST, 2), 256>>>(Wec);
    k_xprep<<<dim3(NST, 256), 256>>>(cnn, asum);
    k_mma<<<148, 256, SMEM_SZ>>>(Wv);
    k_reduceE<<<Bt, 256>>>(bv);
    k_gmax<<<1, 32>>>();
    k_softmax<<<Bt, 256>>>(mask, asum, out);
    k_context<<<dim3(Ct, Bt), 128>>>(cnn, out);
}

// round 8
// speedup vs baseline: 2.6316x; 1.1236x over previous
#include <cuda_runtime.h>
#include <cuda_fp16.h>
#include <stdint.h>
#include <math.h>

#define Bt 32
#define Ct 684
#define Ht 16
#define Wt 64
#define HWt 1024
#define HIDt 256
#define At 512
#define NPATCH 121
#define KCOMB 805
#define NST 13            // 13 stages of k=64
#define NPOS 32768
#define ALPHA_OFF (Bt*Ct)
#define ASUM_OFF  (Bt*Ct + Bt*HWt)

// tiles: X (128 pos x 64 k) fp16 = 16384 B ; W (256 a x 64 k) fp16 = 32768 B
#define XT 16384
#define WT 32768
#define STB (XT + WT)
#define NSLOT 4
#define SMEM_SZ (NSLOT*STB)    // 192 KB
#define NTILE 512              // 256 pos-groups x 2 a-groups (interleaved)

// ---------------- device scratch ----------------
__device__ __align__(1024) unsigned char g_X[(size_t)256 * NST * XT];   // 54.5 MB
__device__ __align__(1024) unsigned char g_W[(size_t)2 * NST * WT];     // 852 KB
__device__ float g_Weff[At * NPATCH];
__device__ float g_query[Bt * At];       // q + bh + bec folded
__device__ float g_Epart[2 * NPOS];
__device__ float g_E[Bt * HWt];
__device__ float g_bmax[Bt];
__device__ float g_gmax;

// ---------------- helpers ----------------
__device__ __forceinline__ uint32_t smem_u32(const void* p) {
    uint32_t a;
    asm("{ .reg .u64 t; cvta.to.shared.u64 t, %1; cvt.u32.u64 %0, t; }" : "=r"(a) : "l"(p));
    return a;
}
__device__ __forceinline__ void mb_init(uint32_t a, uint32_t c) {
    asm volatile("mbarrier.init.shared.b64 [%0], %1;" :: "r"(a), "r"(c) : "memory");
}
__device__ __forceinline__ void mb_arrive(uint32_t a) {
    asm volatile("mbarrier.arrive.shared.b64 _, [%0];" :: "r"(a) : "memory");
}
__device__ __forceinline__ void mb_tx(uint32_t a, uint32_t bytes) {
    asm volatile("mbarrier.arrive.expect_tx.shared.b64 _, [%0], %1;" :: "r"(a), "r"(bytes) : "memory");
}
__device__ __forceinline__ void mb_wait(uint32_t a, uint32_t par) {
    uint32_t d = 0;
    while (!d)
        asm volatile("{ .reg .pred p; mbarrier.try_wait.parity.acquire.cta.shared::cta.b64 p,[%1],%2,0x989680; selp.b32 %0,1,0,p; }"
                     : "=r"(d) : "r"(a), "r"(par) : "memory");
}
__device__ __forceinline__ void blkcp(uint32_t dst, const void* src, uint32_t bytes, uint32_t mbar) {
    asm volatile("cp.async.bulk.shared::cta.global.mbarrier::complete_tx::bytes [%0], [%1], %2, [%3];"
                 :: "r"(dst), "l"(src), "r"(bytes), "r"(mbar) : "memory");
}
#define LDMX4(r0,r1,r2,r3,addr) \
    asm volatile("ldmatrix.sync.aligned.m8n8.x4.shared.b16 {%0,%1,%2,%3}, [%4];" \
                 : "=r"(r0),"=r"(r1),"=r"(r2),"=r"(r3) : "r"(addr))
#define MMA(d,a,b) \
    asm volatile("mma.sync.aligned.m16n8k16.row.col.f32.f16.f16.f32 " \
                 "{%0,%1,%2,%3},{%4,%5,%6,%7},{%8,%9},{%0,%1,%2,%3};" \
                 : "+f"(d[0]),"+f"(d[1]),"+f"(d[2]),"+f"(d[3]) \
                 : "r"(a[0]),"r"(a[1]),"r"(a[2]),"r"(a[3]),"r"(b[0]),"r"(b[1]))

__device__ __forceinline__ uint32_t h2u(float v0, float v1) {
    __half2 h = __floats2half2_rn(v0, v1);
    return *(uint32_t*)&h;
}
__device__ __forceinline__ float ftanh(float x) {
    float e = __expf(2.0f * x);
    return 1.0f - __fdividef(2.0f, e + 1.0f);
}

// ---------------- prep: merged weff (y=0) + query (y=1) ----------------
__global__ void k_small(const float* __restrict__ Waw, const float* __restrict__ Wac,
                        const float* __restrict__ hidden, const float* __restrict__ Wh,
                        const float* __restrict__ bh, const float* __restrict__ bec) {
    if (blockIdx.y == 0) {
        int a = blockIdx.x, j = threadIdx.x;
        if (j >= NPATCH) return;
        float s = 0.f;
        for (int c = 0; c < At; ++c) s = fmaf(Waw[a * At + c], Wac[c * NPATCH + j], s);
        g_Weff[a * NPATCH + j] = s;
    } else {
        int b = blockIdx.x, tid = threadIdx.x;
        if (b >= Bt) return;
        __shared__ float h[HIDt];
        for (int k = tid; k < HIDt; k += 128) h[k] = hidden[b * HIDt + k];
        __syncthreads();
        for (int a = tid; a < At; a += 128) {
            const float* wr = Wh + a * HIDt;
            float s = 0.f;
            #pragma unroll 8
            for (int k = 0; k < HIDt; ++k) s = fmaf(wr[k], h[k], s);
            g_query[b * At + a] = s + bh[a] + bec[a];
        }
    }
}

// ---------------- prep: W tiles [ag][s] 256a x 64k fp16, SW128-swizzled ----------------
// grid (13, 4): each block does 128 a-rows; ag2 = y>>1 selects 256-a group, y&1 the 128-row half.
__global__ void k_wpack(const float* __restrict__ Wec) {
    __shared__ float sm[64][129];
    const int s = blockIdx.x, ag = blockIdx.y, tid = threadIdx.x;
    const int w = tid >> 5, lane = tid & 31;
    #pragma unroll 4
    for (int i = 0; i < 32; ++i) {
        int kk = lane + (i & 1) * 32;
        int a = w + (i >> 1) * 8;
        int k = s * 64 + kk, aa = ag * 128 + a;
        float v = 0.f;
        if (k < Ct) v = Wec[aa * Ct + k];
        else if (k < KCOMB) v = g_Weff[aa * NPATCH + (k - Ct)];
        sm[kk][a] = v;
    }
    __syncthreads();
    unsigned char* tile = g_W + ((size_t)((ag >> 1) * NST + s) << 15);
    const int rbase = (ag & 1) * 128;
    #pragma unroll
    for (int i = 0; i < 4; ++i) {
        int idx = i * 256 + tid;
        int r = idx >> 3, ch = idx & 7;
        uint32_t hv[4];
        #pragma unroll
        for (int j = 0; j < 4; ++j)
            hv[j] = h2u(sm[ch * 8 + 2 * j][r], sm[ch * 8 + 2 * j + 1][r]);
        int r2 = rbase + r;
        uint32_t off = r2 * 128 + ((ch ^ (r2 & 7)) << 4);
        *(uint4*)(tile + off) = make_uint4(hv[0], hv[1], hv[2], hv[3]);
    }
}

// ---------------- prep: X tiles [pg][s] 128pos x 64k fp16, SW128-swizzled ----------------
__global__ void k_xprep(const float* __restrict__ cnn, const float* __restrict__ asum) {
    __shared__ float sm[64][129];
    const int s = blockIdx.x, pg = blockIdx.y, tid = threadIdx.x;
    const int b = pg >> 3;
    #pragma unroll
    for (int i = 0; i < 32; ++i) {
        int idx = i * 256 + tid;
        int kr = idx >> 7, p = idx & 127;
        int posb = (pg & 7) * 128 + p;
        int k = s * 64 + kr;
        float v = 0.f;
        if (k < Ct) {
            v = cnn[(size_t)b * (Ct * HWt) + k * HWt + posb];
        } else if (k < KCOMB) {
            int j = k - Ct;
            int hh = (posb >> 6) + j / 11 - 5;
            int ww = (posb & 63) + j % 11 - 5;
            if (hh >= 0 && hh < Ht && ww >= 0 && ww < Wt) v = asum[b * HWt + hh * Wt + ww];
        }
        sm[kr][p] = v;
    }
    __syncthreads();
    unsigned char* tile = g_X + ((size_t)(pg * NST + s) << 14);
    #pragma unroll
    for (int i = 0; i < 4; ++i) {
        int idx = i * 256 + tid;
        int r = idx >> 3, ch = idx & 7;
        uint32_t hv[4];
        #pragma unroll
        for (int j = 0; j < 4; ++j)
            hv[j] = h2u(sm[ch * 8 + 2 * j][r], sm[ch * 8 + 2 * j + 1][r]);
        uint32_t off = r * 128 + ((ch ^ (r & 7)) << 4);
        *(uint4*)(tile + off) = make_uint4(hv[0], hv[1], hv[2], hv[3]);
    }
}

// ---------------- main: persistent, 4-deep bulk pipeline, 128 pos x 256 a, k=64 stages ----------------
__global__ __launch_bounds__(256, 1)
void k_mma(const float* __restrict__ Wv) {
    extern __shared__ char dsm[];
    __shared__ float qs[256], ws[256], esm[512];
    __shared__ __align__(8) uint64_t mbars[2 * NSLOT];
    const uint32_t sb = smem_u32(dsm);
    const uint32_t mbF = smem_u32(&mbars[0]);
    const uint32_t mbE = mbF + 8 * NSLOT;
    const int tid = threadIdx.x, lane = tid & 31, w = tid >> 5;
    const int wm = w >> 2, wn = w & 3;

    if (tid == 0)
        for (int i = 0; i < NSLOT; ++i) { mb_init(mbF + 8 * i, 1); mb_init(mbE + 8 * i, 1); }
    __syncthreads();

    int tiles[4], ntiles = 0;
    for (int t = blockIdx.x; t < NTILE; t += 148) tiles[ntiles++] = t;
    const int total = ntiles * NST;

    auto issue = [&](int gs) {
        int ti = gs / NST, s = gs - ti * NST;
        int tile = tiles[ti];
        int bx = tile >> 1, by = tile & 1;      // interleaved: adjacent tiles share X
        int slot = gs & (NSLOT - 1), u = gs >> 2;
        mb_wait(mbE + 8 * slot, 1 ^ (u & 1));
        uint32_t fb = mbF + 8 * slot;
        mb_tx(fb, STB);
        blkcp(sb + slot * STB, g_X + ((size_t)(bx * NST + s) << 14), XT, fb);
        blkcp(sb + slot * STB + XT, g_W + ((size_t)(by * NST + s) << 15), WT, fb);
    };

    if (tid == 0)
        for (int gs = 0; gs < 3 && gs < total; ++gs) issue(gs);

    int gs = 0;
    for (int ti = 0; ti < ntiles; ++ti) {
        const int tile = tiles[ti];
        const int bx = tile >> 1, by = tile & 1;
        const int pos0 = bx * 128, a0 = by * 256, b = bx >> 3;

        float acc[4][8][4];
        #pragma unroll
        for (int mt = 0; mt < 4; ++mt)
            #pragma unroll
            for (int nt = 0; nt < 8; ++nt)
                #pragma unroll
                for (int r = 0; r < 4; ++r) acc[mt][nt][r] = 0.f;

        for (int s = 0; s < NST; ++s, ++gs) {
            if (tid == 0 && gs + 3 < total) issue(gs + 3);
            const int slot = gs & (NSLOT - 1), u = gs >> 2;
            mb_wait(mbF + 8 * slot, u & 1);

            const uint32_t xb = sb + slot * STB;
            const uint32_t wb = xb + XT;

            #pragma unroll
            for (int ks = 0; ks < 4; ++ks) {
                uint32_t bf[8][2];
                const int browb = wn * 64 + (lane & 7) + ((lane >> 4) & 1) * 8;
                const int bc = 2 * ks + ((lane >> 3) & 1);
                #pragma unroll
                for (int np = 0; np < 4; ++np) {
                    int r = browb + np * 16;
                    uint32_t boff = r * 128 + ((bc ^ (r & 7)) << 4);
                    LDMX4(bf[np*2][0], bf[np*2][1], bf[np*2+1][0], bf[np*2+1][1], wb + boff);
                }
                const int arow = wm * 64 + (lane & 15);
                const int ac = 2 * ks + (lane >> 4);
                #pragma unroll
                for (int mt = 0; mt < 4; ++mt) {
                    int r = arow + mt * 16;
                    uint32_t aoff = r * 128 + ((ac ^ (r & 7)) << 4);
                    uint32_t af[4];
                    LDMX4(af[0], af[1], af[2], af[3], xb + aoff);
                    #pragma unroll
                    for (int nt = 0; nt < 8; ++nt)
                        MMA(acc[mt][nt], af, bf[nt]);
                }
            }
            __syncthreads();
            if (tid == 0) mb_arrive(mbE + 8 * slot);
        }

        // epilogue: e[pos] = sum_a Wv[a]*tanh(acc + q[b][a])
        qs[tid] = g_query[b * At + a0 + tid];
        ws[tid] = Wv[a0 + tid];
        __syncthreads();

        #pragma unroll
        for (int mt = 0; mt < 4; ++mt) {
            float er0 = 0.f, er1 = 0.f;
            #pragma unroll
            for (int nt = 0; nt < 8; ++nt) {
                int col = wn * 64 + nt * 8 + (lane & 3) * 2;
                float q0 = qs[col], q1 = qs[col + 1];
                float w0 = ws[col], w1 = ws[col + 1];
                er0 = fmaf(w0, ftanh(acc[mt][nt][0] + q0), er0);
                er0 = fmaf(w1, ftanh(acc[mt][nt][1] + q1), er0);
                er1 = fmaf(w0, ftanh(acc[mt][nt][2] + q0), er1);
                er1 = fmaf(w1, ftanh(acc[mt][nt][3] + q1), er1);
            }
            er0 += __shfl_xor_sync(0xffffffffu, er0, 1);
            er0 += __shfl_xor_sync(0xffffffffu, er0, 2);
            er1 += __shfl_xor_sync(0xffffffffu, er1, 1);
            er1 += __shfl_xor_sync(0xffffffffu, er1, 2);
            if ((lane & 3) == 0) {
                int r = wm * 64 + mt * 16 + (lane >> 2);
                esm[r * 4 + wn] = er0;
                esm[(r + 8) * 4 + wn] = er1;
            }
        }
        __syncthreads();
        if (tid < 128)
            g_Epart[by * NPOS + pos0 + tid] =
                esm[tid * 4] + esm[tid * 4 + 1] + esm[tid * 4 + 2] + esm[tid * 4 + 3];
        __syncthreads();
    }
}

// ---------------- tails ----------------
__global__ void k_reduceE(const float* __restrict__ bv) {
    int b = blockIdx.x, tid = threadIdx.x;
    float bvv = bv[0], m = -1e30f;
    for (int p = tid; p < HWt; p += 256) {
        float s = bvv + g_Epart[b * HWt + p] + g_Epart[NPOS + b * HWt + p];
        g_E[b * HWt + p] = s;
        m = fmaxf(m, s);
    }
    __shared__ float sm[256];
    sm[tid] = m; __syncthreads();
    for (int s2 = 128; s2 > 0; s2 >>= 1) { if (tid < s2) sm[tid] = fmaxf(sm[tid], sm[tid + s2]); __syncthreads(); }
    if (tid == 0) g_bmax[b] = sm[0];
}

__global__ void k_gmax() {
    float v = g_bmax[threadIdx.x];
    #pragma unroll
    for (int o = 16; o > 0; o >>= 1) v = fmaxf(v, __shfl_xor_sync(0xffffffffu, v, o));
    if (threadIdx.x == 0) g_gmax = v;
}

__global__ void k_softmax(const float* __restrict__ mask, const float* __restrict__ asum,
                          float* __restrict__ out) {
    int b = blockIdx.x, tid = threadIdx.x;
    __shared__ float ex[HWt];
    __shared__ float sm[256];
    float gm = g_gmax, ls = 0.f;
    for (int p = tid; p < HWt; p += 256) {
        float v = expf(g_E[b * HWt + p] - gm) * mask[b * HWt + p];
        ex[p] = v; ls += v;
    }
    sm[tid] = ls; __syncthreads();
    for (int s2 = 128; s2 > 0; s2 >>= 1) { if (tid < s2) sm[tid] += sm[tid + s2]; __syncthreads(); }
    float inv = 1.f / (sm[0] + 1e-10f);
    for (int p = tid; p < HWt; p += 256) {
        float al = ex[p] * inv;
        out[ALPHA_OFF + b * HWt + p] = al;
        out[ASUM_OFF + b * HWt + p] = al + asum[b * HWt + p];
    }
}

__global__ void k_context(const float* __restrict__ cnn, float* __restrict__ out) {
    int c = blockIdx.x, b = blockIdx.y, tid = threadIdx.x;
    const float* f = cnn + (size_t)(b * Ct + c) * HWt;
    const float* al = out + ALPHA_OFF + b * HWt;
    float s = 0.f;
    for (int p = tid; p < HWt; p += 128) s = fmaf(al[p], f[p], s);
    #pragma unroll
    for (int o = 16; o > 0; o >>= 1) s += __shfl_xor_sync(0xffffffffu, s, o);
    __shared__ float sm[4];
    if ((tid & 31) == 0) sm[tid >> 5] = s;
    __syncthreads();
    if (tid == 0) out[b * Ct + c] = sm[0] + sm[1] + sm[2] + sm[3];
}

// ---------------- launch ----------------
extern "C" void kernel_launch(void* const* d_in, const int* in_sizes, int n_in,
                              void* d_out, int out_size) {
    const float* cnn    = (const float*)d_in[0];
    const float* hidden = (const float*)d_in[1];
    const float* asum   = (const float*)d_in[2];
    const float* mask   = (const float*)d_in[3];
    const float* Wh     = (const float*)d_in[4];
    const float* bh     = (const float*)d_in[5];
    const float* Wec    = (const float*)d_in[6];
    const float* bec    = (const float*)d_in[7];
    const float* Wac    = (const float*)d_in[8];
    const float* Waw    = (const float*)d_in[9];
    const float* Wv     = (const float*)d_in[10];
    const float* bv     = (const float*)d_in[11];
    float* out = (float*)d_out;

    cudaFuncSetAttribute(k_mma, cudaFuncAttributeMaxDynamicSharedMemorySize, SMEM_SZ);

    k_small<<<dim3(At, 2), 128>>>(Waw, Wac, hidden, Wh, bh, bec);   // 1
    k_wpack<<<dim3(NST, 4), 256>>>(Wec);                            // 2
    k_xprep<<<dim3(NST, 256), 256>>>(cnn, asum);                    // 3
    k_mma<<<148, 256, SMEM_SZ>>>(Wv);                               // 4  <- ncu capture slot
    k_reduceE<<<Bt, 256>>>(bv);                                     // 5
    k_gmax<<<1, 32>>>();                                            // 6
    k_softmax<<<Bt, 256>>>(mask, asum, out);                        // 7
    k_context<<<dim3(Ct, Bt), 128>>>(cnn, out);                     // 8
}